// round 3
// baseline (speedup 1.0000x reference)
#include <cuda_runtime.h>
#include <math.h>

// Problem constants
#define BB 4
#define SS 2048
#define DD 1024
#define HH 16
#define HD 64
#define MM (BB*SS)          // 8192

// ---------------- scratch (device globals; no allocation allowed) ----------
__device__ float g_Q[(size_t)BB*HH*SS*HD];   // [b][h][s][d]
__device__ float g_K[(size_t)BB*HH*SS*HD];
__device__ float g_V[(size_t)BB*HH*SS*HD];
__device__ float g_C[(size_t)BB*SS*DD];      // ctx [b][s][h*64+d]

// ---------------- projection / output GEMM ---------------------------------
// Y[m][n] = sum_k X[m][k] * W[n][k] + bias[n]
// mode 0: scatter to [B,H,S,HD] (Q/K/V).  mode 1: row-major [M,N] (ctx->out).
#define GBM 128
#define GBN 128
#define GBK 8

__global__ __launch_bounds__(256) void gemm_btrans(
    const float* __restrict__ X, const float* __restrict__ W,
    const float* __restrict__ bias, float* __restrict__ Y, int mode)
{
    __shared__ float As[GBK][GBM];
    __shared__ float Bs[GBK][GBN];

    const int tid = threadIdx.x;             // 0..255
    const int bm = blockIdx.y * GBM;
    const int bn = blockIdx.x * GBN;
    const int tx = tid & 15;
    const int ty = tid >> 4;

    const int lrow = tid >> 1;               // 0..127
    const int lcol = (tid & 1) * 4;          // 0 or 4

    const float* Xp = X + (size_t)(bm + lrow) * DD + lcol;
    const float* Wp = W + (size_t)(bn + lrow) * DD + lcol;

    float acc[8][8];
    #pragma unroll
    for (int i = 0; i < 8; i++)
        #pragma unroll
        for (int j = 0; j < 8; j++) acc[i][j] = 0.f;

    for (int k0 = 0; k0 < DD; k0 += GBK) {
        float4 a = *(const float4*)(Xp + k0);
        float4 b = *(const float4*)(Wp + k0);
        As[lcol + 0][lrow] = a.x; As[lcol + 1][lrow] = a.y;
        As[lcol + 2][lrow] = a.z; As[lcol + 3][lrow] = a.w;
        Bs[lcol + 0][lrow] = b.x; Bs[lcol + 1][lrow] = b.y;
        Bs[lcol + 2][lrow] = b.z; Bs[lcol + 3][lrow] = b.w;
        __syncthreads();

        #pragma unroll
        for (int k = 0; k < GBK; k++) {
            float ar[8], br[8];
            #pragma unroll
            for (int i = 0; i < 8; i++) ar[i] = As[k][ty * 8 + i];
            #pragma unroll
            for (int j = 0; j < 8; j++) br[j] = Bs[k][tx * 8 + j];
            #pragma unroll
            for (int i = 0; i < 8; i++)
                #pragma unroll
                for (int j = 0; j < 8; j++)
                    acc[i][j] = fmaf(ar[i], br[j], acc[i][j]);
        }
        __syncthreads();
    }

    #pragma unroll
    for (int i = 0; i < 8; i++) {
        const int m = bm + ty * 8 + i;
        #pragma unroll
        for (int j = 0; j < 8; j++) {
            const int n = bn + tx * 8 + j;
            const float v = acc[i][j] + __ldg(&bias[n]);
            if (mode == 0) {
                const int b = m >> 11;        // m / 2048
                const int s = m & 2047;
                const int h = n >> 6;         // n / 64
                const int d = n & 63;
                Y[((((size_t)b * HH + h) * SS) + s) * HD + d] = v;
            } else {
                Y[(size_t)m * DD + n] = v;
            }
        }
    }
}

// ---------------- flash attention (fp32) ------------------------------------
// One block: 64 queries of one (b,h), iterating 32-key tiles.
// 256 threads as 16x16; each owns 4 rows; S tile is 64x32 -> each thread owns
// 4x2 of S. Static smem only (43 KB) -> no cudaFuncSetAttribute needed.
#define AQ 64
#define AK 32
#define QPITCH 68   // floats
#define PPITCH 36

__global__ __launch_bounds__(256) void attn_kernel()
{
    __shared__ float Qs[AQ * QPITCH];                 // 64*68 = 4352
    __shared__ float Ks[AK * QPITCH];                 // 32*68 = 2176
    __shared__ float Vs[AK * QPITCH];                 // 2176
    __shared__ float Ps[AQ * PPITCH];                 // 64*36 = 2304
    // total 11008 floats = 43 KB

    const int tid = threadIdx.x;
    const int qt  = blockIdx.x;           // 0..31
    const int bh  = blockIdx.y;           // 0..63  (= b*16+h)
    const int tx = tid & 15;
    const int ty = tid >> 4;
    const int r0 = ty * 4;
    const int c0 = tx * 2;                // 2 cols of the 32-wide S tile

    const float* Qg = g_Q + (size_t)bh * SS * HD + (size_t)qt * AQ * HD;
    const float* Kg = g_K + (size_t)bh * SS * HD;
    const float* Vg = g_V + (size_t)bh * SS * HD;

    // load Q tile (4096 floats = 1024 float4s, 4 per thread)
    #pragma unroll
    for (int i = 0; i < 4; i++) {
        const int lin = tid + i * 256;    // float4 index
        const int row = lin >> 4;
        const int c4  = (lin & 15) * 4;
        float4 v = *(const float4*)(Qg + row * HD + c4);
        *(float4*)(Qs + row * QPITCH + c4) = v;
    }

    float m_i[4], l_i[4], o[4][4];        // o: 4 rows x 4 head dims (cols tx*4..)
    const int oc0 = tx * 4;               // this thread's head-dim columns for O
    #pragma unroll
    for (int i = 0; i < 4; i++) {
        m_i[i] = -1e30f; l_i[i] = 0.f;
        #pragma unroll
        for (int j = 0; j < 4; j++) o[i][j] = 0.f;
    }

    for (int kt = 0; kt < SS / AK; kt++) {
        // load K,V tiles: 32 rows x 64 floats = 512 float4s, 2 per thread each
        #pragma unroll
        for (int i = 0; i < 2; i++) {
            const int lin = tid + i * 256;
            const int row = lin >> 4;
            const int c4  = (lin & 15) * 4;
            const size_t goff = (size_t)(kt * AK + row) * HD + c4;
            *(float4*)(Ks + row * QPITCH + c4) = *(const float4*)(Kg + goff);
            *(float4*)(Vs + row * QPITCH + c4) = *(const float4*)(Vg + goff);
        }
        __syncthreads();

        // S = Q K^T : this thread's 4x2 patch of the 64x32 tile
        float s[4][2];
        #pragma unroll
        for (int i = 0; i < 4; i++) { s[i][0] = 0.f; s[i][1] = 0.f; }

        for (int k = 0; k < HD; k += 4) {
            float4 q[4], kk[2];
            #pragma unroll
            for (int i = 0; i < 4; i++) q[i]  = *(const float4*)(Qs + (r0 + i) * QPITCH + k);
            #pragma unroll
            for (int j = 0; j < 2; j++) kk[j] = *(const float4*)(Ks + (c0 + j) * QPITCH + k);
            #pragma unroll
            for (int i = 0; i < 4; i++)
                #pragma unroll
                for (int j = 0; j < 2; j++) {
                    s[i][j] = fmaf(q[i].x, kk[j].x, s[i][j]);
                    s[i][j] = fmaf(q[i].y, kk[j].y, s[i][j]);
                    s[i][j] = fmaf(q[i].z, kk[j].z, s[i][j]);
                    s[i][j] = fmaf(q[i].w, kk[j].w, s[i][j]);
                }
        }

        // scale + online softmax (row spread across 16 lanes; shfl stays in half-warp)
        float tmax[4], tsum[4];
        #pragma unroll
        for (int i = 0; i < 4; i++) {
            s[i][0] *= 0.125f;
            s[i][1] *= 0.125f;
            tmax[i] = fmaxf(s[i][0], s[i][1]);
        }
        #pragma unroll
        for (int off = 8; off >= 1; off >>= 1)
            #pragma unroll
            for (int i = 0; i < 4; i++)
                tmax[i] = fmaxf(tmax[i], __shfl_xor_sync(0xffffffffu, tmax[i], off));

        #pragma unroll
        for (int i = 0; i < 4; i++) {
            const float m_new = fmaxf(m_i[i], tmax[i]);
            const float alpha = __expf(m_i[i] - m_new);
            const float p0 = __expf(s[i][0] - m_new);
            const float p1 = __expf(s[i][1] - m_new);
            s[i][0] = p0; s[i][1] = p1;
            tsum[i] = p0 + p1;
            m_i[i] = m_new;
            l_i[i] = l_i[i] * alpha;
            #pragma unroll
            for (int j = 0; j < 4; j++) o[i][j] *= alpha;
        }
        #pragma unroll
        for (int off = 8; off >= 1; off >>= 1)
            #pragma unroll
            for (int i = 0; i < 4; i++)
                tsum[i] += __shfl_xor_sync(0xffffffffu, tsum[i], off);
        #pragma unroll
        for (int i = 0; i < 4; i++) l_i[i] += tsum[i];

        // publish P (64x32)
        #pragma unroll
        for (int i = 0; i < 4; i++) {
            Ps[(r0 + i) * PPITCH + (c0 + 0)] = s[i][0];
            Ps[(r0 + i) * PPITCH + (c0 + 1)] = s[i][1];
        }
        __syncthreads();

        // O += P V : rows r0..r0+3, head-dims oc0..oc0+3
        for (int c = 0; c < AK; c += 4) {
            float4 p4[4], v4[4];
            #pragma unroll
            for (int i = 0; i < 4; i++)  p4[i]  = *(const float4*)(Ps + (r0 + i) * PPITCH + c);
            #pragma unroll
            for (int cc = 0; cc < 4; cc++) v4[cc] = *(const float4*)(Vs + (c + cc) * QPITCH + oc0);
            #pragma unroll
            for (int i = 0; i < 4; i++) {
                o[i][0] = fmaf(p4[i].x, v4[0].x, o[i][0]);
                o[i][0] = fmaf(p4[i].y, v4[1].x, o[i][0]);
                o[i][0] = fmaf(p4[i].z, v4[2].x, o[i][0]);
                o[i][0] = fmaf(p4[i].w, v4[3].x, o[i][0]);
                o[i][1] = fmaf(p4[i].x, v4[0].y, o[i][1]);
                o[i][1] = fmaf(p4[i].y, v4[1].y, o[i][1]);
                o[i][1] = fmaf(p4[i].z, v4[2].y, o[i][1]);
                o[i][1] = fmaf(p4[i].w, v4[3].y, o[i][1]);
                o[i][2] = fmaf(p4[i].x, v4[0].z, o[i][2]);
                o[i][2] = fmaf(p4[i].y, v4[1].z, o[i][2]);
                o[i][2] = fmaf(p4[i].z, v4[2].z, o[i][2]);
                o[i][2] = fmaf(p4[i].w, v4[3].z, o[i][2]);
                o[i][3] = fmaf(p4[i].x, v4[0].w, o[i][3]);
                o[i][3] = fmaf(p4[i].y, v4[1].w, o[i][3]);
                o[i][3] = fmaf(p4[i].z, v4[2].w, o[i][3]);
                o[i][3] = fmaf(p4[i].w, v4[3].w, o[i][3]);
            }
        }
        __syncthreads();
    }

    // epilogue: normalize + write ctx [b][s][h*64+d]
    const int b = bh >> 4;
    const int h = bh & 15;
    #pragma unroll
    for (int i = 0; i < 4; i++) {
        const int q = qt * AQ + r0 + i;
        const float inv = 1.0f / l_i[i];
        float4 v;
        v.x = o[i][0] * inv; v.y = o[i][1] * inv;
        v.z = o[i][2] * inv; v.w = o[i][3] * inv;
        *(float4*)(g_C + ((size_t)b * SS + q) * DD + h * HD + oc0) = v;
    }
}

// ---------------- launch -----------------------------------------------------
extern "C" void kernel_launch(void* const* d_in, const int* in_sizes, int n_in,
                              void* d_out, int out_size)
{
    (void)in_sizes; (void)n_in; (void)out_size;
    const float* x  = (const float*)d_in[0];
    const float* Wq = (const float*)d_in[1];
    const float* bq = (const float*)d_in[2];
    const float* Wk = (const float*)d_in[3];
    const float* bk = (const float*)d_in[4];
    const float* Wv = (const float*)d_in[5];
    const float* bv = (const float*)d_in[6];
    const float* Wo = (const float*)d_in[7];
    const float* bo = (const float*)d_in[8];

    float *pQ, *pK, *pV, *pC;
    cudaGetSymbolAddress((void**)&pQ, g_Q);
    cudaGetSymbolAddress((void**)&pK, g_K);
    cudaGetSymbolAddress((void**)&pV, g_V);
    cudaGetSymbolAddress((void**)&pC, g_C);

    const dim3 ggrid(DD / GBN, MM / GBM);   // (8, 64)

    gemm_btrans<<<ggrid, 256>>>(x, Wq, bq, pQ, 0);
    gemm_btrans<<<ggrid, 256>>>(x, Wk, bk, pK, 0);
    gemm_btrans<<<ggrid, 256>>>(x, Wv, bv, pV, 0);

    attn_kernel<<<dim3(SS / AQ, BB * HH), 256>>>();

    gemm_btrans<<<ggrid, 256>>>(pC, Wo, bo, (float*)d_out, 1);
}

// round 4
// speedup vs baseline: 3.0274x; 3.0274x over previous
#include <cuda_runtime.h>
#include <math.h>
#include <stdint.h>

// Problem constants
#define BB 4
#define SS 2048
#define DD 1024
#define HH 16
#define HD 64
#define MM (BB*SS)          // 8192

// ---------------- scratch (device globals; no allocation allowed) ----------
__device__ float g_Q[(size_t)BB*HH*SS*HD];   // [b][h][s][d]
__device__ float g_K[(size_t)BB*HH*SS*HD];
__device__ float g_V[(size_t)BB*HH*SS*HD];
__device__ float g_C[(size_t)BB*SS*DD];      // ctx [b][s][h*64+d]

// ---------------- tf32 mma helpers -----------------------------------------
__device__ __forceinline__ uint32_t f2tf(float x) {
    uint32_t r;
    asm("cvt.rna.tf32.f32 %0, %1;" : "=r"(r) : "f"(x));
    return r;
}
__device__ __forceinline__ void mma_tf32(float d[4], const uint32_t a[4],
                                         const uint32_t b[2], const float c[4]) {
    asm volatile(
        "mma.sync.aligned.m16n8k8.row.col.f32.tf32.tf32.f32 "
        "{%0,%1,%2,%3},{%4,%5,%6,%7},{%8,%9},{%10,%11,%12,%13};"
        : "=f"(d[0]), "=f"(d[1]), "=f"(d[2]), "=f"(d[3])
        : "r"(a[0]), "r"(a[1]), "r"(a[2]), "r"(a[3]),
          "r"(b[0]), "r"(b[1]),
          "f"(c[0]), "f"(c[1]), "f"(c[2]), "f"(c[3]));
}
__device__ __forceinline__ float u2f(float v) { return v; }

// ---------------- projection / output GEMM (tf32 tensor cores) -------------
// Y[m][n] = sum_k X[m][k] * W[n][k] + bias[n]
// mode 0: scatter to [B,H,S,HD] (Q/K/V).  mode 1: row-major [M,N] (ctx->out).
#define TBM 128
#define TBN 128
#define TBK 32
#define GPITCH 36    // floats; bank = 4*g + q -> conflict-free frag loads

__global__ __launch_bounds__(256) void gemm_tc(
    const float* __restrict__ X, const float* __restrict__ W,
    const float* __restrict__ bias, float* __restrict__ Y, int mode)
{
    __shared__ float As[TBM * GPITCH];
    __shared__ float Bs[TBN * GPITCH];

    const int tid  = threadIdx.x;
    const int lane = tid & 31;
    const int wid  = tid >> 5;      // 0..7
    const int wm   = wid & 3;       // warp row  (4)
    const int wn   = wid >> 2;      // warp col  (2)
    const int g    = lane >> 2;     // 0..7
    const int q    = lane & 3;      // 0..3
    const int bm   = blockIdx.y * TBM;
    const int bn   = blockIdx.x * TBN;

    float acc[2][8][4];
    #pragma unroll
    for (int rg = 0; rg < 2; rg++)
        #pragma unroll
        for (int nt = 0; nt < 8; nt++)
            #pragma unroll
            for (int e = 0; e < 4; e++) acc[rg][nt][e] = 0.f;

    for (int k0 = 0; k0 < DD; k0 += TBK) {
        // stage A and B tiles (tf32-rounded). 128 rows x 8 float4 each.
        #pragma unroll
        for (int i = 0; i < 4; i++) {
            const int lin = tid + i * 256;        // 0..1023
            const int row = lin >> 3;
            const int c4  = (lin & 7) * 4;
            float4 a = *(const float4*)(X + (size_t)(bm + row) * DD + k0 + c4);
            float4 b = *(const float4*)(W + (size_t)(bn + row) * DD + k0 + c4);
            float4 ar, br;
            ar.x = __uint_as_float(f2tf(a.x)); ar.y = __uint_as_float(f2tf(a.y));
            ar.z = __uint_as_float(f2tf(a.z)); ar.w = __uint_as_float(f2tf(a.w));
            br.x = __uint_as_float(f2tf(b.x)); br.y = __uint_as_float(f2tf(b.y));
            br.z = __uint_as_float(f2tf(b.z)); br.w = __uint_as_float(f2tf(b.w));
            *(float4*)(As + row * GPITCH + c4) = ar;
            *(float4*)(Bs + row * GPITCH + c4) = br;
        }
        __syncthreads();

        #pragma unroll
        for (int kc = 0; kc < 4; kc++) {
            const int kk = kc * 8;
            uint32_t af[2][4], bf[8][2];
            #pragma unroll
            for (int rg = 0; rg < 2; rg++) {
                const int r = wm * 32 + rg * 16;
                af[rg][0] = __float_as_uint(As[(r + g)     * GPITCH + kk + q]);
                af[rg][1] = __float_as_uint(As[(r + g + 8) * GPITCH + kk + q]);
                af[rg][2] = __float_as_uint(As[(r + g)     * GPITCH + kk + q + 4]);
                af[rg][3] = __float_as_uint(As[(r + g + 8) * GPITCH + kk + q + 4]);
            }
            #pragma unroll
            for (int nt = 0; nt < 8; nt++) {
                const int n = wn * 64 + nt * 8;
                bf[nt][0] = __float_as_uint(Bs[(n + g) * GPITCH + kk + q]);
                bf[nt][1] = __float_as_uint(Bs[(n + g) * GPITCH + kk + q + 4]);
            }
            #pragma unroll
            for (int rg = 0; rg < 2; rg++)
                #pragma unroll
                for (int nt = 0; nt < 8; nt++)
                    mma_tf32(acc[rg][nt], af[rg], bf[nt], acc[rg][nt]);
        }
        __syncthreads();
    }

    // epilogue: c0:(g,2q) c1:(g,2q+1) c2:(g+8,2q) c3:(g+8,2q+1)
    #pragma unroll
    for (int rg = 0; rg < 2; rg++) {
        #pragma unroll
        for (int nt = 0; nt < 8; nt++) {
            const int n = bn + wn * 64 + nt * 8 + 2 * q;
            const float b0 = __ldg(&bias[n]);
            const float b1 = __ldg(&bias[n + 1]);
            #pragma unroll
            for (int half = 0; half < 2; half++) {
                const int m = bm + wm * 32 + rg * 16 + g + half * 8;
                const float v0 = acc[rg][nt][half * 2 + 0] + b0;
                const float v1 = acc[rg][nt][half * 2 + 1] + b1;
                if (mode == 0) {
                    const int bb = m >> 11;
                    const int s  = m & 2047;
                    const int h  = n >> 6;
                    const int d  = n & 63;
                    float2* p = (float2*)(Y + ((((size_t)bb * HH + h) * SS) + s) * HD + d);
                    *p = make_float2(v0, v1);
                } else {
                    *(float2*)(Y + (size_t)m * DD + n) = make_float2(v0, v1);
                }
            }
        }
    }
}

// ---------------- flash attention (tf32 tensor cores) ------------------------
// Block: 64 queries of one (b,h). 4 warps, warp owns 16 query rows.
// Key tiles of 64. S and P live entirely in mma fragments (no P smem round-trip).
#define APITCH 68   // floats; bank = 4*g + q offset pattern -> conflict-free

__global__ __launch_bounds__(128) void attn_tc()
{
    __shared__ float Ks[64 * APITCH];   // also Q staging before main loop
    __shared__ float Vs[64 * APITCH];

    const int tid  = threadIdx.x;
    const int lane = tid & 31;
    const int w    = tid >> 5;          // 0..3
    const int g    = lane >> 2;
    const int q    = lane & 3;
    const int qt   = blockIdx.x;        // 0..31 (64 queries each)
    const int bh   = blockIdx.y;        // 0..63

    const float* Qg = g_Q + (size_t)bh * SS * HD + (size_t)qt * 64 * HD;
    const float* Kg = g_K + (size_t)bh * SS * HD;
    const float* Vg = g_V + (size_t)bh * SS * HD;

    // ---- stage Q (tf32-rounded) and build per-warp Q fragments -------------
    #pragma unroll
    for (int i = 0; i < 8; i++) {
        const int lin = tid + i * 128;     // 0..1023 float4 index
        const int row = lin >> 4;
        const int c4  = (lin & 15) * 4;
        float4 v = *(const float4*)(Qg + row * HD + c4);
        float4 r;
        r.x = __uint_as_float(f2tf(v.x)); r.y = __uint_as_float(f2tf(v.y));
        r.z = __uint_as_float(f2tf(v.z)); r.w = __uint_as_float(f2tf(v.w));
        *(float4*)(Ks + row * APITCH + c4) = r;
    }
    __syncthreads();

    uint32_t qa[8][4];
    {
        const int r = w * 16;
        #pragma unroll
        for (int kc = 0; kc < 8; kc++) {
            const int kk = kc * 8;
            qa[kc][0] = __float_as_uint(Ks[(r + g)     * APITCH + kk + q]);
            qa[kc][1] = __float_as_uint(Ks[(r + g + 8) * APITCH + kk + q]);
            qa[kc][2] = __float_as_uint(Ks[(r + g)     * APITCH + kk + q + 4]);
            qa[kc][3] = __float_as_uint(Ks[(r + g + 8) * APITCH + kk + q + 4]);
        }
    }
    __syncthreads();   // done with Q staging buffer

    float oc[8][4];
    #pragma unroll
    for (int nt = 0; nt < 8; nt++)
        #pragma unroll
        for (int e = 0; e < 4; e++) oc[nt][e] = 0.f;
    float m_lo = -1e30f, m_hi = -1e30f, l_lo = 0.f, l_hi = 0.f;

    const float CS = 0.125f * 1.44269504088896f;  // scale * log2(e)
    const int s0 = (lane & ~3) | (q >> 1);        // quad shuffle sources
    const int s1 = s0 + 2;
    const bool odd = (q & 1);

    for (int kt = 0; kt < SS / 64; kt++) {
        // ---- stage K,V tiles (tf32-rounded) --------------------------------
        #pragma unroll
        for (int i = 0; i < 8; i++) {
            const int lin = tid + i * 128;
            const int row = lin >> 4;
            const int c4  = (lin & 15) * 4;
            const size_t goff = (size_t)(kt * 64 + row) * HD + c4;
            float4 kv = *(const float4*)(Kg + goff);
            float4 vv = *(const float4*)(Vg + goff);
            float4 kr, vr;
            kr.x = __uint_as_float(f2tf(kv.x)); kr.y = __uint_as_float(f2tf(kv.y));
            kr.z = __uint_as_float(f2tf(kv.z)); kr.w = __uint_as_float(f2tf(kv.w));
            vr.x = __uint_as_float(f2tf(vv.x)); vr.y = __uint_as_float(f2tf(vv.y));
            vr.z = __uint_as_float(f2tf(vv.z)); vr.w = __uint_as_float(f2tf(vv.w));
            *(float4*)(Ks + row * APITCH + c4) = kr;
            *(float4*)(Vs + row * APITCH + c4) = vr;
        }
        __syncthreads();

        // ---- S = Q K^T (warp's 16 x 64) ------------------------------------
        float sc[8][4];
        #pragma unroll
        for (int nt = 0; nt < 8; nt++)
            #pragma unroll
            for (int e = 0; e < 4; e++) sc[nt][e] = 0.f;

        #pragma unroll
        for (int kc = 0; kc < 8; kc++) {
            const int kk = kc * 8;
            #pragma unroll
            for (int nt = 0; nt < 8; nt++) {
                uint32_t bf[2];
                bf[0] = __float_as_uint(Ks[(nt * 8 + g) * APITCH + kk + q]);
                bf[1] = __float_as_uint(Ks[(nt * 8 + g) * APITCH + kk + q + 4]);
                mma_tf32(sc[nt], qa[kc], bf, sc[nt]);
            }
        }

        // ---- online softmax in fragment layout (base-2 domain) -------------
        float tl = -1e30f, th = -1e30f;
        #pragma unroll
        for (int nt = 0; nt < 8; nt++) {
            sc[nt][0] *= CS; sc[nt][1] *= CS; sc[nt][2] *= CS; sc[nt][3] *= CS;
            tl = fmaxf(tl, fmaxf(sc[nt][0], sc[nt][1]));
            th = fmaxf(th, fmaxf(sc[nt][2], sc[nt][3]));
        }
        tl = fmaxf(tl, __shfl_xor_sync(0xffffffffu, tl, 1));
        tl = fmaxf(tl, __shfl_xor_sync(0xffffffffu, tl, 2));
        th = fmaxf(th, __shfl_xor_sync(0xffffffffu, th, 1));
        th = fmaxf(th, __shfl_xor_sync(0xffffffffu, th, 2));

        const float ml = fmaxf(m_lo, tl);
        const float mh = fmaxf(m_hi, th);
        const float al = exp2f(m_lo - ml);
        const float ah = exp2f(m_hi - mh);

        float suml = 0.f, sumh = 0.f;
        #pragma unroll
        for (int nt = 0; nt < 8; nt++) {
            sc[nt][0] = exp2f(sc[nt][0] - ml);
            sc[nt][1] = exp2f(sc[nt][1] - ml);
            sc[nt][2] = exp2f(sc[nt][2] - mh);
            sc[nt][3] = exp2f(sc[nt][3] - mh);
            suml += sc[nt][0] + sc[nt][1];
            sumh += sc[nt][2] + sc[nt][3];
        }
        suml += __shfl_xor_sync(0xffffffffu, suml, 1);
        suml += __shfl_xor_sync(0xffffffffu, suml, 2);
        sumh += __shfl_xor_sync(0xffffffffu, sumh, 1);
        sumh += __shfl_xor_sync(0xffffffffu, sumh, 2);

        l_lo = l_lo * al + suml;
        l_hi = l_hi * ah + sumh;
        m_lo = ml; m_hi = mh;

        #pragma unroll
        for (int nt = 0; nt < 8; nt++) {
            oc[nt][0] *= al; oc[nt][1] *= al;
            oc[nt][2] *= ah; oc[nt][3] *= ah;
        }

        // ---- O += P V: rearrange P (C-layout -> A-layout) via quad shuffles -
        #pragma unroll
        for (int kc = 0; kc < 8; kc++) {
            const float t00 = __shfl_sync(0xffffffffu, sc[kc][0], s0);
            const float t01 = __shfl_sync(0xffffffffu, sc[kc][1], s0);
            const float t02 = __shfl_sync(0xffffffffu, sc[kc][0], s1);
            const float t03 = __shfl_sync(0xffffffffu, sc[kc][1], s1);
            const float t10 = __shfl_sync(0xffffffffu, sc[kc][2], s0);
            const float t11 = __shfl_sync(0xffffffffu, sc[kc][3], s0);
            const float t12 = __shfl_sync(0xffffffffu, sc[kc][2], s1);
            const float t13 = __shfl_sync(0xffffffffu, sc[kc][3], s1);
            uint32_t pa[4];
            pa[0] = f2tf(odd ? t01 : t00);
            pa[1] = f2tf(odd ? t11 : t10);
            pa[2] = f2tf(odd ? t03 : t02);
            pa[3] = f2tf(odd ? t13 : t12);
            const int kk = kc * 8;
            #pragma unroll
            for (int nt = 0; nt < 8; nt++) {
                uint32_t vb[2];
                vb[0] = __float_as_uint(Vs[(kk + q)     * APITCH + nt * 8 + g]);
                vb[1] = __float_as_uint(Vs[(kk + q + 4) * APITCH + nt * 8 + g]);
                mma_tf32(oc[nt], pa, vb, oc[nt]);
            }
        }
        __syncthreads();   // before next tile overwrites Ks/Vs
    }

    // ---- epilogue: normalize, write ctx [b][s][h*64+d] ----------------------
    const float il = 1.0f / l_lo;
    const float ih = 1.0f / l_hi;
    const int b = bh >> 4;
    const int h = bh & 15;
    const int row_lo = qt * 64 + w * 16 + g;
    #pragma unroll
    for (int nt = 0; nt < 8; nt++) {
        const int col = h * 64 + nt * 8 + 2 * q;
        *(float2*)(g_C + ((size_t)b * SS + row_lo) * DD + col) =
            make_float2(oc[nt][0] * il, oc[nt][1] * il);
        *(float2*)(g_C + ((size_t)b * SS + row_lo + 8) * DD + col) =
            make_float2(oc[nt][2] * ih, oc[nt][3] * ih);
    }
}

// ---------------- launch -----------------------------------------------------
extern "C" void kernel_launch(void* const* d_in, const int* in_sizes, int n_in,
                              void* d_out, int out_size)
{
    (void)in_sizes; (void)n_in; (void)out_size;
    const float* x  = (const float*)d_in[0];
    const float* Wq = (const float*)d_in[1];
    const float* bq = (const float*)d_in[2];
    const float* Wk = (const float*)d_in[3];
    const float* bk = (const float*)d_in[4];
    const float* Wv = (const float*)d_in[5];
    const float* bv = (const float*)d_in[6];
    const float* Wo = (const float*)d_in[7];
    const float* bo = (const float*)d_in[8];

    float *pQ, *pK, *pV, *pC;
    cudaGetSymbolAddress((void**)&pQ, g_Q);
    cudaGetSymbolAddress((void**)&pK, g_K);
    cudaGetSymbolAddress((void**)&pV, g_V);
    cudaGetSymbolAddress((void**)&pC, g_C);

    const dim3 ggrid(DD / TBN, MM / TBM);   // (8, 64)

    gemm_tc<<<ggrid, 256>>>(x, Wq, bq, pQ, 0);
    gemm_tc<<<ggrid, 256>>>(x, Wk, bk, pK, 0);
    gemm_tc<<<ggrid, 256>>>(x, Wv, bv, pV, 0);

    attn_tc<<<dim3(SS / 64, BB * HH), 128>>>();

    gemm_tc<<<ggrid, 256>>>(pC, Wo, bo, (float*)d_out, 1);
}

// round 5
// speedup vs baseline: 7.5635x; 2.4983x over previous
#include <cuda_runtime.h>
#include <cuda_fp16.h>
#include <math.h>
#include <stdint.h>

// Problem constants
#define BB 4
#define SS 2048
#define DD 1024
#define HH 16
#define HD 64
#define MM (BB*SS)          // 8192

// ---------------- scratch (device globals; no allocation allowed) ----------
__device__ __half g_Xh[(size_t)MM*DD];            // x in half
__device__ __half g_Wh[4][(size_t)DD*DD];         // Wq,Wk,Wv,Wo in half
__device__ __half g_Qh[(size_t)BB*HH*SS*HD];      // [b][h][s][d]
__device__ __half g_Kh[(size_t)BB*HH*SS*HD];
__device__ __half g_Vh[(size_t)BB*HH*SS*HD];
__device__ __half g_Ch[(size_t)MM*DD];            // ctx [b][s][h*64+d]

// ---------------- helpers ----------------------------------------------------
__device__ __forceinline__ uint32_t s2u(const void* p) {
    return (uint32_t)__cvta_generic_to_shared(p);
}
__device__ __forceinline__ void ldm_x4(uint32_t r[4], uint32_t a) {
    asm volatile("ldmatrix.sync.aligned.m8n8.x4.shared.b16 {%0,%1,%2,%3}, [%4];"
        : "=r"(r[0]), "=r"(r[1]), "=r"(r[2]), "=r"(r[3]) : "r"(a));
}
__device__ __forceinline__ void ldm_x4t(uint32_t r[4], uint32_t a) {
    asm volatile("ldmatrix.sync.aligned.m8n8.x4.trans.shared.b16 {%0,%1,%2,%3}, [%4];"
        : "=r"(r[0]), "=r"(r[1]), "=r"(r[2]), "=r"(r[3]) : "r"(a));
}
__device__ __forceinline__ void mma16816(float d[4], const uint32_t a[4],
                                         const uint32_t b0, const uint32_t b1,
                                         const float c[4]) {
    asm volatile("mma.sync.aligned.m16n8k16.row.col.f32.f16.f16.f32 "
        "{%0,%1,%2,%3},{%4,%5,%6,%7},{%8,%9},{%10,%11,%12,%13};"
        : "=f"(d[0]), "=f"(d[1]), "=f"(d[2]), "=f"(d[3])
        : "r"(a[0]), "r"(a[1]), "r"(a[2]), "r"(a[3]), "r"(b0), "r"(b1),
          "f"(c[0]), "f"(c[1]), "f"(c[2]), "f"(c[3]));
}
__device__ __forceinline__ uint32_t packh2(float x, float y) {
    __half2 h = __floats2half2_rn(x, y);
    return *reinterpret_cast<uint32_t*>(&h);
}
__device__ __forceinline__ float ex2f(float x) {
    float r; asm("ex2.approx.ftz.f32 %0, %1;" : "=f"(r) : "f"(x)); return r;
}
__device__ __forceinline__ void cpa16(uint32_t d, const void* g) {
    asm volatile("cp.async.cg.shared.global [%0], [%1], 16;" :: "r"(d), "l"(g));
}
__device__ __forceinline__ void cpa_commit() { asm volatile("cp.async.commit_group;"); }
__device__ __forceinline__ void cpa_wait0()  { asm volatile("cp.async.wait_group 0;"); }

// ---------------- fp32 -> fp16 conversion ------------------------------------
__global__ __launch_bounds__(256) void f2h(const float* __restrict__ in,
                                           __half* __restrict__ out, int n) {
    const int i = (blockIdx.x * 256 + threadIdx.x) * 4;
    if (i < n) {
        float4 v = *(const float4*)(in + i);
        *(__half2*)(out + i)     = __floats2half2_rn(v.x, v.y);
        *(__half2*)(out + i + 2) = __floats2half2_rn(v.z, v.w);
    }
}

// ---------------- GEMM (fp16 mma + ldmatrix + cp.async) ---------------------
// Y[m][n] = sum_k X[m][k] * W[n][k] + bias[n]
// mode 0: scatter half to [B,H,S,HD].  mode 1: row-major fp32 [M,N].
#define GP 40   // halves; 80B rows -> conflict-free ldmatrix phases

__global__ __launch_bounds__(256) void gemm_h(
    const __half* __restrict__ X, const __half* __restrict__ W,
    const float* __restrict__ bias, void* __restrict__ Yv, int mode)
{
    __shared__ __half As[2][128 * GP];
    __shared__ __half Bs[2][128 * GP];

    const int tid  = threadIdx.x;
    const int lane = tid & 31;
    const int wid  = tid >> 5;
    const int wm   = wid & 3;           // 4 warp rows of 32
    const int wn   = wid >> 2;          // 2 warp cols of 64
    const int g    = lane >> 2;
    const int q    = lane & 3;
    const int bm   = blockIdx.y * 128;
    const int bn   = blockIdx.x * 128;

    const int srow = tid >> 2;          // staging row base (+64 for i=1)
    const int sc8  = (tid & 3) * 8;     // halves
    const int frow  = lane & 15;        // ldmatrix row within 16
    const int fcol8 = (lane >> 4) * 8;  // ldmatrix col half-offset

    float acc[2][8][4];
    #pragma unroll
    for (int rg = 0; rg < 2; rg++)
        #pragma unroll
        for (int nt = 0; nt < 8; nt++)
            #pragma unroll
            for (int e = 0; e < 4; e++) acc[rg][nt][e] = 0.f;

    // prologue: stage k0=0 into buf 0
    #pragma unroll
    for (int i = 0; i < 2; i++) {
        const int row = srow + i * 64;
        cpa16(s2u(&As[0][row * GP + sc8]), X + (size_t)(bm + row) * DD + sc8);
        cpa16(s2u(&Bs[0][row * GP + sc8]), W + (size_t)(bn + row) * DD + sc8);
    }
    cpa_commit();

    for (int it = 0; it < DD / 32; it++) {
        cpa_wait0();
        __syncthreads();
        const int buf = it & 1;
        if (it + 1 < DD / 32) {
            const int k0 = (it + 1) * 32;
            #pragma unroll
            for (int i = 0; i < 2; i++) {
                const int row = srow + i * 64;
                cpa16(s2u(&As[buf ^ 1][row * GP + sc8]),
                      X + (size_t)(bm + row) * DD + k0 + sc8);
                cpa16(s2u(&Bs[buf ^ 1][row * GP + sc8]),
                      W + (size_t)(bn + row) * DD + k0 + sc8);
            }
            cpa_commit();
        }

        #pragma unroll
        for (int ks = 0; ks < 2; ks++) {
            const int kk = ks * 16 + fcol8;
            uint32_t af[2][4], bq4[4][4];
            #pragma unroll
            for (int rg = 0; rg < 2; rg++)
                ldm_x4(af[rg], s2u(&As[buf][(wm * 32 + rg * 16 + frow) * GP + kk]));
            #pragma unroll
            for (int ng = 0; ng < 4; ng++)
                ldm_x4(bq4[ng], s2u(&Bs[buf][(wn * 64 + ng * 16 + frow) * GP + kk]));
            #pragma unroll
            for (int rg = 0; rg < 2; rg++)
                #pragma unroll
                for (int ng = 0; ng < 4; ng++) {
                    // regs: r0=b0(oct0) r1=b0(oct1) r2=b1(oct0) r3=b1(oct1)
                    mma16816(acc[rg][ng * 2 + 0], af[rg], bq4[ng][0], bq4[ng][2],
                             acc[rg][ng * 2 + 0]);
                    mma16816(acc[rg][ng * 2 + 1], af[rg], bq4[ng][1], bq4[ng][3],
                             acc[rg][ng * 2 + 1]);
                }
        }
    }

    // epilogue: c0:(g,2q) c1:(g,2q+1) c2:(g+8,2q) c3:(g+8,2q+1)
    #pragma unroll
    for (int rg = 0; rg < 2; rg++) {
        #pragma unroll
        for (int nt = 0; nt < 8; nt++) {
            const int n = bn + wn * 64 + nt * 8 + 2 * q;
            const float b0 = __ldg(&bias[n]);
            const float b1 = __ldg(&bias[n + 1]);
            #pragma unroll
            for (int half_ = 0; half_ < 2; half_++) {
                const int m = bm + wm * 32 + rg * 16 + g + half_ * 8;
                const float v0 = acc[rg][nt][half_ * 2 + 0] + b0;
                const float v1 = acc[rg][nt][half_ * 2 + 1] + b1;
                if (mode == 0) {
                    const int bb = m >> 11;
                    const int s  = m & 2047;
                    const int h  = n >> 6;
                    const int d  = n & 63;
                    __half* Y = (__half*)Yv;
                    *(__half2*)(Y + ((((size_t)bb * HH + h) * SS) + s) * HD + d) =
                        __floats2half2_rn(v0, v1);
                } else {
                    float* Y = (float*)Yv;
                    *(float2*)(Y + (size_t)m * DD + n) = make_float2(v0, v1);
                }
            }
        }
    }
}

// ---------------- flash attention (fp16 mma + ldmatrix) ----------------------
// Block: 64 queries of one (b,h). 4 warps x 16 query rows. 64-key tiles.
// P stays in registers: fp16 C-frag == A-frag layout (no shuffles, no smem).
#define KP 72   // halves; 144B rows -> conflict-free ldmatrix phases

__global__ __launch_bounds__(128) void attn_h()
{
    __shared__ __half Ks[64 * KP];   // also Q staging before main loop
    __shared__ __half Vs[64 * KP];

    const int tid  = threadIdx.x;
    const int lane = tid & 31;
    const int w    = tid >> 5;
    const int g    = lane >> 2;
    const int q    = lane & 3;
    const int qt   = blockIdx.x;     // 0..31
    const int bh   = blockIdx.y;     // 0..63
    const int frow  = lane & 15;
    const int fcol8 = (lane >> 4) * 8;

    const __half* Qg = g_Qh + (size_t)bh * SS * HD + (size_t)qt * 64 * HD;
    const __half* Kg = g_Kh + (size_t)bh * SS * HD;
    const __half* Vg = g_Vh + (size_t)bh * SS * HD;

    // ---- stage Q, build per-warp A fragments --------------------------------
    #pragma unroll
    for (int i = 0; i < 4; i++) {
        const int lin = tid + i * 128;          // 0..511 (16B chunks)
        const int row = lin >> 3;
        const int c8  = (lin & 7) * 8;
        *(uint4*)(&Ks[row * KP + c8]) = *(const uint4*)(Qg + row * HD + c8);
    }
    __syncthreads();

    uint32_t qa[4][4];
    #pragma unroll
    for (int kc = 0; kc < 4; kc++)
        ldm_x4(qa[kc], s2u(&Ks[(w * 16 + frow) * KP + kc * 16 + fcol8]));
    __syncthreads();   // Q staging buffer free for K tiles

    float oc[8][4];
    #pragma unroll
    for (int nt = 0; nt < 8; nt++)
        #pragma unroll
        for (int e = 0; e < 4; e++) oc[nt][e] = 0.f;
    float m_lo = -1e30f, m_hi = -1e30f, l_lo = 0.f, l_hi = 0.f;

    const float CS = 0.125f * 1.44269504088896f;  // scale * log2(e)

    for (int kt = 0; kt < SS / 64; kt++) {
        // ---- stage K,V tiles ------------------------------------------------
        #pragma unroll
        for (int i = 0; i < 4; i++) {
            const int lin = tid + i * 128;
            const int row = lin >> 3;
            const int c8  = (lin & 7) * 8;
            const size_t goff = (size_t)(kt * 64 + row) * HD + c8;
            *(uint4*)(&Ks[row * KP + c8]) = *(const uint4*)(Kg + goff);
            *(uint4*)(&Vs[row * KP + c8]) = *(const uint4*)(Vg + goff);
        }
        __syncthreads();

        // ---- S = Q K^T (warp's 16 x 64) ------------------------------------
        float sc[8][4];
        #pragma unroll
        for (int nt = 0; nt < 8; nt++)
            #pragma unroll
            for (int e = 0; e < 4; e++) sc[nt][e] = 0.f;

        #pragma unroll
        for (int kc = 0; kc < 4; kc++) {
            const int kk = kc * 16 + fcol8;
            #pragma unroll
            for (int ng = 0; ng < 4; ng++) {
                uint32_t bk[4];
                ldm_x4(bk, s2u(&Ks[(ng * 16 + frow) * KP + kk]));
                mma16816(sc[ng * 2 + 0], qa[kc], bk[0], bk[2], sc[ng * 2 + 0]);
                mma16816(sc[ng * 2 + 1], qa[kc], bk[1], bk[3], sc[ng * 2 + 1]);
            }
        }

        // ---- online softmax in fragment layout (base-2 domain) -------------
        float tl = -1e30f, th = -1e30f;
        #pragma unroll
        for (int nt = 0; nt < 8; nt++) {
            sc[nt][0] *= CS; sc[nt][1] *= CS; sc[nt][2] *= CS; sc[nt][3] *= CS;
            tl = fmaxf(tl, fmaxf(sc[nt][0], sc[nt][1]));
            th = fmaxf(th, fmaxf(sc[nt][2], sc[nt][3]));
        }
        tl = fmaxf(tl, __shfl_xor_sync(0xffffffffu, tl, 1));
        tl = fmaxf(tl, __shfl_xor_sync(0xffffffffu, tl, 2));
        th = fmaxf(th, __shfl_xor_sync(0xffffffffu, th, 1));
        th = fmaxf(th, __shfl_xor_sync(0xffffffffu, th, 2));

        const float ml = fmaxf(m_lo, tl);
        const float mh = fmaxf(m_hi, th);
        const float al = ex2f(m_lo - ml);
        const float ah = ex2f(m_hi - mh);

        float suml = 0.f, sumh = 0.f;
        #pragma unroll
        for (int nt = 0; nt < 8; nt++) {
            sc[nt][0] = ex2f(sc[nt][0] - ml);
            sc[nt][1] = ex2f(sc[nt][1] - ml);
            sc[nt][2] = ex2f(sc[nt][2] - mh);
            sc[nt][3] = ex2f(sc[nt][3] - mh);
            suml += sc[nt][0] + sc[nt][1];
            sumh += sc[nt][2] + sc[nt][3];
        }
        suml += __shfl_xor_sync(0xffffffffu, suml, 1);
        suml += __shfl_xor_sync(0xffffffffu, suml, 2);
        sumh += __shfl_xor_sync(0xffffffffu, sumh, 1);
        sumh += __shfl_xor_sync(0xffffffffu, sumh, 2);

        l_lo = l_lo * al + suml;
        l_hi = l_hi * ah + sumh;
        m_lo = ml; m_hi = mh;

        #pragma unroll
        for (int nt = 0; nt < 8; nt++) {
            oc[nt][0] *= al; oc[nt][1] *= al;
            oc[nt][2] *= ah; oc[nt][3] *= ah;
        }

        // ---- O += P V (P: C-frag -> A-frag by register packing only) -------
        #pragma unroll
        for (int kc2 = 0; kc2 < 4; kc2++) {
            uint32_t pa[4];
            pa[0] = packh2(sc[2 * kc2][0],     sc[2 * kc2][1]);      // row g,   k0-7
            pa[1] = packh2(sc[2 * kc2][2],     sc[2 * kc2][3]);      // row g+8, k0-7
            pa[2] = packh2(sc[2 * kc2 + 1][0], sc[2 * kc2 + 1][1]);  // row g,   k8-15
            pa[3] = packh2(sc[2 * kc2 + 1][2], sc[2 * kc2 + 1][3]);  // row g+8, k8-15
            #pragma unroll
            for (int ng = 0; ng < 4; ng++) {
                uint32_t bv[4];
                ldm_x4t(bv, s2u(&Vs[(kc2 * 16 + frow) * KP + ng * 16 + fcol8]));
                mma16816(oc[ng * 2 + 0], pa, bv[0], bv[1], oc[ng * 2 + 0]);
                mma16816(oc[ng * 2 + 1], pa, bv[2], bv[3], oc[ng * 2 + 1]);
            }
        }
        __syncthreads();   // before next tile overwrites Ks/Vs
    }

    // ---- epilogue: normalize, write half ctx [b][s][h*64+d] -----------------
    const float il = 1.0f / l_lo;
    const float ih = 1.0f / l_hi;
    const int b = bh >> 4;
    const int h = bh & 15;
    const int row_lo = qt * 64 + w * 16 + g;
    #pragma unroll
    for (int nt = 0; nt < 8; nt++) {
        const int col = h * 64 + nt * 8 + 2 * q;
        *(__half2*)(g_Ch + ((size_t)b * SS + row_lo) * DD + col) =
            __floats2half2_rn(oc[nt][0] * il, oc[nt][1] * il);
        *(__half2*)(g_Ch + ((size_t)b * SS + row_lo + 8) * DD + col) =
            __floats2half2_rn(oc[nt][2] * ih, oc[nt][3] * ih);
    }
}

// ---------------- launch -----------------------------------------------------
extern "C" void kernel_launch(void* const* d_in, const int* in_sizes, int n_in,
                              void* d_out, int out_size)
{
    (void)in_sizes; (void)n_in; (void)out_size;
    const float* x  = (const float*)d_in[0];
    const float* Wq = (const float*)d_in[1];
    const float* bq = (const float*)d_in[2];
    const float* Wk = (const float*)d_in[3];
    const float* bk = (const float*)d_in[4];
    const float* Wv = (const float*)d_in[5];
    const float* bv = (const float*)d_in[6];
    const float* Wo = (const float*)d_in[7];
    const float* bo = (const float*)d_in[8];

    __half *pXh, *pWh, *pQh, *pKh, *pVh, *pCh;
    cudaGetSymbolAddress((void**)&pXh, g_Xh);
    cudaGetSymbolAddress((void**)&pWh, g_Wh);
    cudaGetSymbolAddress((void**)&pQh, g_Qh);
    cudaGetSymbolAddress((void**)&pKh, g_Kh);
    cudaGetSymbolAddress((void**)&pVh, g_Vh);
    cudaGetSymbolAddress((void**)&pCh, g_Ch);
    __half* pW0 = pWh + 0 * (size_t)DD * DD;
    __half* pW1 = pWh + 1 * (size_t)DD * DD;
    __half* pW2 = pWh + 2 * (size_t)DD * DD;
    __half* pW3 = pWh + 3 * (size_t)DD * DD;

    // convert inputs to half
    f2h<<<(MM * DD / 4 + 255) / 256, 256>>>(x,  pXh, MM * DD);
    f2h<<<(DD * DD / 4 + 255) / 256, 256>>>(Wq, pW0, DD * DD);
    f2h<<<(DD * DD / 4 + 255) / 256, 256>>>(Wk, pW1, DD * DD);
    f2h<<<(DD * DD / 4 + 255) / 256, 256>>>(Wv, pW2, DD * DD);
    f2h<<<(DD * DD / 4 + 255) / 256, 256>>>(Wo, pW3, DD * DD);

    const dim3 ggrid(DD / 128, MM / 128);   // (8, 64)
    gemm_h<<<ggrid, 256>>>(pXh, pW0, bq, pQh, 0);
    gemm_h<<<ggrid, 256>>>(pXh, pW1, bk, pKh, 0);
    gemm_h<<<ggrid, 256>>>(pXh, pW2, bv, pVh, 0);

    attn_h<<<dim3(SS / 64, BB * HH), 128>>>();

    gemm_h<<<ggrid, 256>>>(pCh, pW3, bo, d_out, 1);
}

// round 6
// speedup vs baseline: 8.2333x; 1.0886x over previous
#include <cuda_runtime.h>
#include <cuda_fp16.h>
#include <math.h>
#include <stdint.h>

// Problem constants
#define BB 4
#define SS 2048
#define DD 1024
#define HH 16
#define HD 64
#define MM (BB*SS)          // 8192

// ---------------- scratch (device globals; no allocation allowed) ----------
__device__ __half g_Xh[(size_t)MM*DD];            // x in half
__device__ __half g_Wh[4][(size_t)DD*DD];         // Wq,Wk,Wv,Wo in half
__device__ __half g_Qh[(size_t)BB*HH*SS*HD];      // [b][h][s][d]
__device__ __half g_Kh[(size_t)BB*HH*SS*HD];
__device__ __half g_Vh[(size_t)BB*HH*SS*HD];
__device__ __half g_Ch[(size_t)MM*DD];            // ctx [b][s][h*64+d]

// ---------------- helpers ----------------------------------------------------
__device__ __forceinline__ uint32_t s2u(const void* p) {
    return (uint32_t)__cvta_generic_to_shared(p);
}
__device__ __forceinline__ void ldm_x4(uint32_t r[4], uint32_t a) {
    asm volatile("ldmatrix.sync.aligned.m8n8.x4.shared.b16 {%0,%1,%2,%3}, [%4];"
        : "=r"(r[0]), "=r"(r[1]), "=r"(r[2]), "=r"(r[3]) : "r"(a));
}
__device__ __forceinline__ void ldm_x4t(uint32_t r[4], uint32_t a) {
    asm volatile("ldmatrix.sync.aligned.m8n8.x4.trans.shared.b16 {%0,%1,%2,%3}, [%4];"
        : "=r"(r[0]), "=r"(r[1]), "=r"(r[2]), "=r"(r[3]) : "r"(a));
}
__device__ __forceinline__ void mma16816(float d[4], const uint32_t a[4],
                                         const uint32_t b0, const uint32_t b1,
                                         const float c[4]) {
    asm volatile("mma.sync.aligned.m16n8k16.row.col.f32.f16.f16.f32 "
        "{%0,%1,%2,%3},{%4,%5,%6,%7},{%8,%9},{%10,%11,%12,%13};"
        : "=f"(d[0]), "=f"(d[1]), "=f"(d[2]), "=f"(d[3])
        : "r"(a[0]), "r"(a[1]), "r"(a[2]), "r"(a[3]), "r"(b0), "r"(b1),
          "f"(c[0]), "f"(c[1]), "f"(c[2]), "f"(c[3]));
}
__device__ __forceinline__ uint32_t packh2(float x, float y) {
    __half2 h = __floats2half2_rn(x, y);
    return *reinterpret_cast<uint32_t*>(&h);
}
__device__ __forceinline__ float ex2f(float x) {
    float r; asm("ex2.approx.ftz.f32 %0, %1;" : "=f"(r) : "f"(x)); return r;
}
__device__ __forceinline__ void cpa16(uint32_t d, const void* g) {
    asm volatile("cp.async.cg.shared.global [%0], [%1], 16;" :: "r"(d), "l"(g));
}
__device__ __forceinline__ void cpa_commit() { asm volatile("cp.async.commit_group;"); }
__device__ __forceinline__ void cpa_wait0()  { asm volatile("cp.async.wait_group 0;"); }

// ---------------- fp32 -> fp16 conversion ------------------------------------
__global__ __launch_bounds__(256) void f2h(const float* __restrict__ in,
                                           __half* __restrict__ out, int n) {
    const int i = (blockIdx.x * 256 + threadIdx.x) * 4;
    if (i < n) {
        float4 v = *(const float4*)(in + i);
        *(__half2*)(out + i)     = __floats2half2_rn(v.x, v.y);
        *(__half2*)(out + i + 2) = __floats2half2_rn(v.z, v.w);
    }
}

// ---------------- GEMM body (fp16 mma + ldmatrix + 2-stage cp.async) --------
// Y[m][n] = sum_k X[m][k] * W[n][k] + bias[n]
// mode 0: scatter half to [B,H,S,HD].  mode 1: row-major fp32 [M,N].
#define GP 40   // halves; 80B rows -> conflict-free ldmatrix phases

__device__ __forceinline__ void gemm_body(
    const __half* __restrict__ X, const __half* __restrict__ W,
    const float* __restrict__ bias, void* __restrict__ Yv, int mode,
    __half* As, __half* Bs)                       // each 2 * 128 * GP halves
{
    const int tid  = threadIdx.x;
    const int lane = tid & 31;
    const int wid  = tid >> 5;
    const int wm   = wid & 3;           // 4 warp rows of 32
    const int wn   = wid >> 2;          // 2 warp cols of 64
    const int g    = lane >> 2;
    const int q    = lane & 3;
    const int bm   = blockIdx.y * 128;
    const int bn   = blockIdx.x * 128;
    const int SB   = 128 * GP;          // stage stride

    const int srow = tid >> 2;          // staging row base (+64 for i=1)
    const int sc8  = (tid & 3) * 8;     // halves
    const int frow  = lane & 15;        // ldmatrix row within 16
    const int fcol8 = (lane >> 4) * 8;  // ldmatrix col half-offset

    float acc[2][8][4];
    #pragma unroll
    for (int rg = 0; rg < 2; rg++)
        #pragma unroll
        for (int nt = 0; nt < 8; nt++)
            #pragma unroll
            for (int e = 0; e < 4; e++) acc[rg][nt][e] = 0.f;

    // prologue: stage k0=0 into buf 0
    #pragma unroll
    for (int i = 0; i < 2; i++) {
        const int row = srow + i * 64;
        cpa16(s2u(&As[row * GP + sc8]), X + (size_t)(bm + row) * DD + sc8);
        cpa16(s2u(&Bs[row * GP + sc8]), W + (size_t)(bn + row) * DD + sc8);
    }
    cpa_commit();

    for (int it = 0; it < DD / 32; it++) {
        cpa_wait0();
        __syncthreads();
        const int buf = it & 1;
        if (it + 1 < DD / 32) {
            const int k0 = (it + 1) * 32;
            #pragma unroll
            for (int i = 0; i < 2; i++) {
                const int row = srow + i * 64;
                cpa16(s2u(&As[(buf ^ 1) * SB + row * GP + sc8]),
                      X + (size_t)(bm + row) * DD + k0 + sc8);
                cpa16(s2u(&Bs[(buf ^ 1) * SB + row * GP + sc8]),
                      W + (size_t)(bn + row) * DD + k0 + sc8);
            }
            cpa_commit();
        }

        #pragma unroll
        for (int ks = 0; ks < 2; ks++) {
            const int kk = ks * 16 + fcol8;
            uint32_t af[2][4], bq4[4][4];
            #pragma unroll
            for (int rg = 0; rg < 2; rg++)
                ldm_x4(af[rg], s2u(&As[buf * SB + (wm * 32 + rg * 16 + frow) * GP + kk]));
            #pragma unroll
            for (int ng = 0; ng < 4; ng++)
                ldm_x4(bq4[ng], s2u(&Bs[buf * SB + (wn * 64 + ng * 16 + frow) * GP + kk]));
            #pragma unroll
            for (int rg = 0; rg < 2; rg++)
                #pragma unroll
                for (int ng = 0; ng < 4; ng++) {
                    mma16816(acc[rg][ng * 2 + 0], af[rg], bq4[ng][0], bq4[ng][2],
                             acc[rg][ng * 2 + 0]);
                    mma16816(acc[rg][ng * 2 + 1], af[rg], bq4[ng][1], bq4[ng][3],
                             acc[rg][ng * 2 + 1]);
                }
        }
    }

    // epilogue: c0:(g,2q) c1:(g,2q+1) c2:(g+8,2q) c3:(g+8,2q+1)
    #pragma unroll
    for (int rg = 0; rg < 2; rg++) {
        #pragma unroll
        for (int nt = 0; nt < 8; nt++) {
            const int n = bn + wn * 64 + nt * 8 + 2 * q;
            const float b0 = __ldg(&bias[n]);
            const float b1 = __ldg(&bias[n + 1]);
            #pragma unroll
            for (int half_ = 0; half_ < 2; half_++) {
                const int m = bm + wm * 32 + rg * 16 + g + half_ * 8;
                const float v0 = acc[rg][nt][half_ * 2 + 0] + b0;
                const float v1 = acc[rg][nt][half_ * 2 + 1] + b1;
                if (mode == 0) {
                    const int bb = m >> 11;
                    const int s  = m & 2047;
                    const int h  = n >> 6;
                    const int d  = n & 63;
                    __half* Y = (__half*)Yv;
                    *(__half2*)(Y + ((((size_t)bb * HH + h) * SS) + s) * HD + d) =
                        __floats2half2_rn(v0, v1);
                } else {
                    float* Y = (float*)Yv;
                    *(float2*)(Y + (size_t)m * DD + n) = make_float2(v0, v1);
                }
            }
        }
    }
}

// fused QKV: blockIdx.z selects {Q,K,V}
__global__ __launch_bounds__(256) void gemm_qkv(
    const float* __restrict__ b0, const float* __restrict__ b1,
    const float* __restrict__ b2)
{
    __shared__ __half As[2 * 128 * GP];
    __shared__ __half Bs[2 * 128 * GP];
    const int z = blockIdx.z;
    const float* bias = (z == 0) ? b0 : (z == 1) ? b1 : b2;
    __half* Y = (z == 0) ? g_Qh : (z == 1) ? g_Kh : g_Vh;
    gemm_body(g_Xh, g_Wh[z], bias, Y, 0, As, Bs);
}

// output projection: ctx @ Wo^T + bo -> fp32 d_out
__global__ __launch_bounds__(256) void gemm_out(
    const float* __restrict__ bias, float* __restrict__ out)
{
    __shared__ __half As[2 * 128 * GP];
    __shared__ __half Bs[2 * 128 * GP];
    gemm_body(g_Ch, g_Wh[3], bias, out, 1, As, Bs);
}

// ---------------- flash attention (fp16 mma, 128q/block, dbl-buffered K/V) --
#define KP 72   // halves; 144B rows -> conflict-free ldmatrix phases
#define KVSTRIDE (64 * KP)

__global__ __launch_bounds__(256) void attn_h()
{
    // KV[0],KV[1] = K buffers; KV[2],KV[3] = V buffers. Q staged over KV[0..1].
    __shared__ __half KV[4 * KVSTRIDE];   // 36864 B

    const int tid  = threadIdx.x;
    const int lane = tid & 31;
    const int w    = tid >> 5;          // 0..7
    const int g    = lane >> 2;
    const int q    = lane & 3;
    const int qt   = blockIdx.x;        // 0..15 (128 queries each)
    const int bh   = blockIdx.y;        // 0..63
    const int frow  = lane & 15;
    const int fcol8 = (lane >> 4) * 8;

    const __half* Qg = g_Qh + (size_t)bh * SS * HD + (size_t)qt * 128 * HD;
    const __half* Kg = g_Kh + (size_t)bh * SS * HD;
    const __half* Vg = g_Vh + (size_t)bh * SS * HD;

    // ---- stage Q (128 x 64) into KV[0..1] region, build per-warp A frags ----
    #pragma unroll
    for (int i = 0; i < 4; i++) {
        const int lin = tid + i * 256;          // 0..1023 16B chunks
        const int row = lin >> 3;
        const int c8  = (lin & 7) * 8;
        *(uint4*)(&KV[row * KP + c8]) = *(const uint4*)(Qg + row * HD + c8);
    }
    __syncthreads();

    uint32_t qa[4][4];
    #pragma unroll
    for (int kc = 0; kc < 4; kc++)
        ldm_x4(qa[kc], s2u(&KV[(w * 16 + frow) * KP + kc * 16 + fcol8]));
    __syncthreads();   // Q staging region free for K buffers

    float oc[8][4];
    #pragma unroll
    for (int nt = 0; nt < 8; nt++)
        #pragma unroll
        for (int e = 0; e < 4; e++) oc[nt][e] = 0.f;
    float m_lo = -1e30f, m_hi = -1e30f, l_lo = 0.f, l_hi = 0.f;

    const float CS = 0.125f * 1.44269504088896f;  // scale * log2(e)

    // prologue: stage kt=0 K/V into buffer 0
    #pragma unroll
    for (int i = 0; i < 2; i++) {
        const int lin = tid + i * 256;          // 0..511 chunks (64 rows x 8)
        const int row = lin >> 3;
        const int c8  = (lin & 7) * 8;
        cpa16(s2u(&KV[0 * KVSTRIDE + row * KP + c8]), Kg + (size_t)row * HD + c8);
        cpa16(s2u(&KV[2 * KVSTRIDE + row * KP + c8]), Vg + (size_t)row * HD + c8);
    }
    cpa_commit();

    for (int kt = 0; kt < SS / 64; kt++) {
        cpa_wait0();
        __syncthreads();
        const int buf = kt & 1;
        if (kt + 1 < SS / 64) {
            const size_t base = (size_t)(kt + 1) * 64 * HD;
            #pragma unroll
            for (int i = 0; i < 2; i++) {
                const int lin = tid + i * 256;
                const int row = lin >> 3;
                const int c8  = (lin & 7) * 8;
                cpa16(s2u(&KV[(buf ^ 1) * KVSTRIDE + row * KP + c8]),
                      Kg + base + (size_t)row * HD + c8);
                cpa16(s2u(&KV[(2 + (buf ^ 1)) * KVSTRIDE + row * KP + c8]),
                      Vg + base + (size_t)row * HD + c8);
            }
            cpa_commit();
        }
        const __half* Ks = &KV[buf * KVSTRIDE];
        const __half* Vs = &KV[(2 + buf) * KVSTRIDE];

        // ---- S = Q K^T (warp's 16 x 64) ------------------------------------
        float sc[8][4];
        #pragma unroll
        for (int nt = 0; nt < 8; nt++)
            #pragma unroll
            for (int e = 0; e < 4; e++) sc[nt][e] = 0.f;

        #pragma unroll
        for (int kc = 0; kc < 4; kc++) {
            const int kk = kc * 16 + fcol8;
            #pragma unroll
            for (int ng = 0; ng < 4; ng++) {
                uint32_t bk[4];
                ldm_x4(bk, s2u(&Ks[(ng * 16 + frow) * KP + kk]));
                mma16816(sc[ng * 2 + 0], qa[kc], bk[0], bk[2], sc[ng * 2 + 0]);
                mma16816(sc[ng * 2 + 1], qa[kc], bk[1], bk[3], sc[ng * 2 + 1]);
            }
        }

        // ---- online softmax in fragment layout (base-2 domain) -------------
        float tl = -1e30f, th = -1e30f;
        #pragma unroll
        for (int nt = 0; nt < 8; nt++) {
            sc[nt][0] *= CS; sc[nt][1] *= CS; sc[nt][2] *= CS; sc[nt][3] *= CS;
            tl = fmaxf(tl, fmaxf(sc[nt][0], sc[nt][1]));
            th = fmaxf(th, fmaxf(sc[nt][2], sc[nt][3]));
        }
        tl = fmaxf(tl, __shfl_xor_sync(0xffffffffu, tl, 1));
        tl = fmaxf(tl, __shfl_xor_sync(0xffffffffu, tl, 2));
        th = fmaxf(th, __shfl_xor_sync(0xffffffffu, th, 1));
        th = fmaxf(th, __shfl_xor_sync(0xffffffffu, th, 2));

        const float ml = fmaxf(m_lo, tl);
        const float mh = fmaxf(m_hi, th);
        const float al = ex2f(m_lo - ml);
        const float ah = ex2f(m_hi - mh);

        float suml = 0.f, sumh = 0.f;
        #pragma unroll
        for (int nt = 0; nt < 8; nt++) {
            sc[nt][0] = ex2f(sc[nt][0] - ml);
            sc[nt][1] = ex2f(sc[nt][1] - ml);
            sc[nt][2] = ex2f(sc[nt][2] - mh);
            sc[nt][3] = ex2f(sc[nt][3] - mh);
            suml += sc[nt][0] + sc[nt][1];
            sumh += sc[nt][2] + sc[nt][3];
        }
        suml += __shfl_xor_sync(0xffffffffu, suml, 1);
        suml += __shfl_xor_sync(0xffffffffu, suml, 2);
        sumh += __shfl_xor_sync(0xffffffffu, sumh, 1);
        sumh += __shfl_xor_sync(0xffffffffu, sumh, 2);

        l_lo = l_lo * al + suml;
        l_hi = l_hi * ah + sumh;
        m_lo = ml; m_hi = mh;

        #pragma unroll
        for (int nt = 0; nt < 8; nt++) {
            oc[nt][0] *= al; oc[nt][1] *= al;
            oc[nt][2] *= ah; oc[nt][3] *= ah;
        }

        // ---- O += P V (P: C-frag -> A-frag by register packing only) -------
        #pragma unroll
        for (int kc2 = 0; kc2 < 4; kc2++) {
            uint32_t pa[4];
            pa[0] = packh2(sc[2 * kc2][0],     sc[2 * kc2][1]);
            pa[1] = packh2(sc[2 * kc2][2],     sc[2 * kc2][3]);
            pa[2] = packh2(sc[2 * kc2 + 1][0], sc[2 * kc2 + 1][1]);
            pa[3] = packh2(sc[2 * kc2 + 1][2], sc[2 * kc2 + 1][3]);
            #pragma unroll
            for (int ng = 0; ng < 4; ng++) {
                uint32_t bv[4];
                ldm_x4t(bv, s2u(&Vs[(kc2 * 16 + frow) * KP + ng * 16 + fcol8]));
                mma16816(oc[ng * 2 + 0], pa, bv[0], bv[1], oc[ng * 2 + 0]);
                mma16816(oc[ng * 2 + 1], pa, bv[2], bv[3], oc[ng * 2 + 1]);
            }
        }
        // no trailing sync: next iter's head-sync guards buffer reuse
    }

    // ---- epilogue: normalize, write half ctx [b][s][h*64+d] -----------------
    const float il = 1.0f / l_lo;
    const float ih = 1.0f / l_hi;
    const int b = bh >> 4;
    const int h = bh & 15;
    const int row_lo = qt * 128 + w * 16 + g;
    #pragma unroll
    for (int nt = 0; nt < 8; nt++) {
        const int col = h * 64 + nt * 8 + 2 * q;
        *(__half2*)(g_Ch + ((size_t)b * SS + row_lo) * DD + col) =
            __floats2half2_rn(oc[nt][0] * il, oc[nt][1] * il);
        *(__half2*)(g_Ch + ((size_t)b * SS + row_lo + 8) * DD + col) =
            __floats2half2_rn(oc[nt][2] * ih, oc[nt][3] * ih);
    }
}

// ---------------- launch -----------------------------------------------------
extern "C" void kernel_launch(void* const* d_in, const int* in_sizes, int n_in,
                              void* d_out, int out_size)
{
    (void)in_sizes; (void)n_in; (void)out_size;
    const float* x  = (const float*)d_in[0];
    const float* Wq = (const float*)d_in[1];
    const float* bq = (const float*)d_in[2];
    const float* Wk = (const float*)d_in[3];
    const float* bk = (const float*)d_in[4];
    const float* Wv = (const float*)d_in[5];
    const float* bv = (const float*)d_in[6];
    const float* Wo = (const float*)d_in[7];
    const float* bo = (const float*)d_in[8];

    __half *pXh, *pWh;
    cudaGetSymbolAddress((void**)&pXh, g_Xh);
    cudaGetSymbolAddress((void**)&pWh, g_Wh);
    __half* pW0 = pWh + 0 * (size_t)DD * DD;
    __half* pW1 = pWh + 1 * (size_t)DD * DD;
    __half* pW2 = pWh + 2 * (size_t)DD * DD;
    __half* pW3 = pWh + 3 * (size_t)DD * DD;

    // convert inputs to half
    f2h<<<(MM * DD / 4 + 255) / 256, 256>>>(x,  pXh, MM * DD);
    f2h<<<(DD * DD / 4 + 255) / 256, 256>>>(Wq, pW0, DD * DD);
    f2h<<<(DD * DD / 4 + 255) / 256, 256>>>(Wk, pW1, DD * DD);
    f2h<<<(DD * DD / 4 + 255) / 256, 256>>>(Wv, pW2, DD * DD);
    f2h<<<(DD * DD / 4 + 255) / 256, 256>>>(Wo, pW3, DD * DD);

    gemm_qkv<<<dim3(DD / 128, MM / 128, 3), 256>>>(bq, bk, bv);

    attn_h<<<dim3(SS / 128, BB * HH), 256>>>();

    gemm_out<<<dim3(DD / 128, MM / 128), 256>>>(bo, (float*)d_out);
}

// round 8
// speedup vs baseline: 8.5492x; 1.0384x over previous
#include <cuda_runtime.h>
#include <cuda_fp16.h>
#include <math.h>
#include <stdint.h>

// Problem constants
#define BB 4
#define SS 2048
#define DD 1024
#define HH 16
#define HD 64
#define MM (BB*SS)          // 8192

// ---------------- scratch (device globals; no allocation allowed) ----------
__device__ __half g_Xh[(size_t)MM*DD];            // x in half
__device__ __half g_Wh[4][(size_t)DD*DD];         // Wq,Wk,Wv,Wo in half
__device__ __half g_Qh[(size_t)BB*HH*SS*HD];      // [b][h][s][d]
__device__ __half g_Kh[(size_t)BB*HH*SS*HD];
__device__ __half g_Vh[(size_t)BB*HH*SS*HD];
__device__ __half g_Ch[(size_t)MM*DD];            // ctx [b][s][h*64+d]

// ---------------- helpers ----------------------------------------------------
__device__ __forceinline__ uint32_t s2u(const void* p) {
    return (uint32_t)__cvta_generic_to_shared(p);
}
__device__ __forceinline__ void ldm_x4(uint32_t r[4], uint32_t a) {
    asm volatile("ldmatrix.sync.aligned.m8n8.x4.shared.b16 {%0,%1,%2,%3}, [%4];"
        : "=r"(r[0]), "=r"(r[1]), "=r"(r[2]), "=r"(r[3]) : "r"(a));
}
__device__ __forceinline__ void ldm_x4t(uint32_t r[4], uint32_t a) {
    asm volatile("ldmatrix.sync.aligned.m8n8.x4.trans.shared.b16 {%0,%1,%2,%3}, [%4];"
        : "=r"(r[0]), "=r"(r[1]), "=r"(r[2]), "=r"(r[3]) : "r"(a));
}
__device__ __forceinline__ void mma16816(float d[4], const uint32_t a[4],
                                         const uint32_t b0, const uint32_t b1,
                                         const float c[4]) {
    asm volatile("mma.sync.aligned.m16n8k16.row.col.f32.f16.f16.f32 "
        "{%0,%1,%2,%3},{%4,%5,%6,%7},{%8,%9},{%10,%11,%12,%13};"
        : "=f"(d[0]), "=f"(d[1]), "=f"(d[2]), "=f"(d[3])
        : "r"(a[0]), "r"(a[1]), "r"(a[2]), "r"(a[3]), "r"(b0), "r"(b1),
          "f"(c[0]), "f"(c[1]), "f"(c[2]), "f"(c[3]));
}
__device__ __forceinline__ uint32_t packh2(float x, float y) {
    __half2 h = __floats2half2_rn(x, y);
    return *reinterpret_cast<uint32_t*>(&h);
}
__device__ __forceinline__ float ex2f(float x) {
    float r; asm("ex2.approx.ftz.f32 %0, %1;" : "=f"(r) : "f"(x)); return r;
}
__device__ __forceinline__ void cpa16(uint32_t d, const void* g) {
    asm volatile("cp.async.cg.shared.global [%0], [%1], 16;" :: "r"(d), "l"(g));
}
__device__ __forceinline__ void cpa_commit() { asm volatile("cp.async.commit_group;"); }
__device__ __forceinline__ void cpa_wait0()  { asm volatile("cp.async.wait_group 0;"); }

// ---------------- fp32 -> fp16 conversion (all 5 tensors, one launch) --------
// blocks [0,8192): x.  blocks [8192, 8192+4096): weights, 1024 blocks each.
__global__ __launch_bounds__(256) void f2h_all(
    const float* __restrict__ x,
    const float* __restrict__ w0, const float* __restrict__ w1,
    const float* __restrict__ w2, const float* __restrict__ w3)
{
    const float* src;
    __half* dst;
    int chunk;
    if (blockIdx.x < 8192) {
        src = x; dst = g_Xh; chunk = blockIdx.x;
    } else {
        const int wi = (blockIdx.x - 8192) >> 10;
        chunk = (blockIdx.x - 8192) & 1023;
        src = (wi == 0) ? w0 : (wi == 1) ? w1 : (wi == 2) ? w2 : w3;
        dst = g_Wh[wi];
    }
    const int i = (chunk * 256 + threadIdx.x) * 4;
    float4 v = *(const float4*)(src + i);
    *(__half2*)(dst + i)     = __floats2half2_rn(v.x, v.y);
    *(__half2*)(dst + i + 2) = __floats2half2_rn(v.z, v.w);
}

// ---------------- GEMM body (fp16 mma + ldmatrix + 2-stage cp.async) --------
// Y[m][n] = sum_k X[m][k] * W[n][k] + bias[n]
// mode 0: scatter half to [B,H,S,HD].  mode 1: row-major fp32 [M,N].
#define GP 40   // halves; 80B rows -> conflict-free ldmatrix phases

__device__ __forceinline__ void gemm_body(
    const __half* __restrict__ X, const __half* __restrict__ W,
    const float* __restrict__ bias, void* __restrict__ Yv, int mode,
    __half* As, __half* Bs)                       // each 2 * 128 * GP halves
{
    const int tid  = threadIdx.x;
    const int lane = tid & 31;
    const int wid  = tid >> 5;
    const int wm   = wid & 3;           // 4 warp rows of 32
    const int wn   = wid >> 2;          // 2 warp cols of 64
    const int g    = lane >> 2;
    const int q    = lane & 3;
    const int bm   = blockIdx.y * 128;
    const int bn   = blockIdx.x * 128;
    const int SB   = 128 * GP;          // stage stride

    const int srow = tid >> 2;          // staging row base (+64 for i=1)
    const int sc8  = (tid & 3) * 8;     // halves
    const int frow  = lane & 15;        // ldmatrix row within 16
    const int fcol8 = (lane >> 4) * 8;  // ldmatrix col half-offset

    float acc[2][8][4];
    #pragma unroll
    for (int rg = 0; rg < 2; rg++)
        #pragma unroll
        for (int nt = 0; nt < 8; nt++)
            #pragma unroll
            for (int e = 0; e < 4; e++) acc[rg][nt][e] = 0.f;

    // prologue: stage k0=0 into buf 0
    #pragma unroll
    for (int i = 0; i < 2; i++) {
        const int row = srow + i * 64;
        cpa16(s2u(&As[row * GP + sc8]), X + (size_t)(bm + row) * DD + sc8);
        cpa16(s2u(&Bs[row * GP + sc8]), W + (size_t)(bn + row) * DD + sc8);
    }
    cpa_commit();

    for (int it = 0; it < DD / 32; it++) {
        cpa_wait0();
        __syncthreads();
        const int buf = it & 1;
        if (it + 1 < DD / 32) {
            const int k0 = (it + 1) * 32;
            #pragma unroll
            for (int i = 0; i < 2; i++) {
                const int row = srow + i * 64;
                cpa16(s2u(&As[(buf ^ 1) * SB + row * GP + sc8]),
                      X + (size_t)(bm + row) * DD + k0 + sc8);
                cpa16(s2u(&Bs[(buf ^ 1) * SB + row * GP + sc8]),
                      W + (size_t)(bn + row) * DD + k0 + sc8);
            }
            cpa_commit();
        }

        #pragma unroll
        for (int ks = 0; ks < 2; ks++) {
            const int kk = ks * 16 + fcol8;
            uint32_t af[2][4], bq4[4][4];
            #pragma unroll
            for (int rg = 0; rg < 2; rg++)
                ldm_x4(af[rg], s2u(&As[buf * SB + (wm * 32 + rg * 16 + frow) * GP + kk]));
            #pragma unroll
            for (int ng = 0; ng < 4; ng++)
                ldm_x4(bq4[ng], s2u(&Bs[buf * SB + (wn * 64 + ng * 16 + frow) * GP + kk]));
            #pragma unroll
            for (int rg = 0; rg < 2; rg++)
                #pragma unroll
                for (int ng = 0; ng < 4; ng++) {
                    mma16816(acc[rg][ng * 2 + 0], af[rg], bq4[ng][0], bq4[ng][2],
                             acc[rg][ng * 2 + 0]);
                    mma16816(acc[rg][ng * 2 + 1], af[rg], bq4[ng][1], bq4[ng][3],
                             acc[rg][ng * 2 + 1]);
                }
        }
    }

    // epilogue: c0:(g,2q) c1:(g,2q+1) c2:(g+8,2q) c3:(g+8,2q+1)
    #pragma unroll
    for (int rg = 0; rg < 2; rg++) {
        #pragma unroll
        for (int nt = 0; nt < 8; nt++) {
            const int n = bn + wn * 64 + nt * 8 + 2 * q;
            const float b0 = __ldg(&bias[n]);
            const float b1 = __ldg(&bias[n + 1]);
            #pragma unroll
            for (int half_ = 0; half_ < 2; half_++) {
                const int m = bm + wm * 32 + rg * 16 + g + half_ * 8;
                const float v0 = acc[rg][nt][half_ * 2 + 0] + b0;
                const float v1 = acc[rg][nt][half_ * 2 + 1] + b1;
                if (mode == 0) {
                    const int bb = m >> 11;
                    const int s  = m & 2047;
                    const int h  = n >> 6;
                    const int d  = n & 63;
                    __half* Y = (__half*)Yv;
                    *(__half2*)(Y + ((((size_t)bb * HH + h) * SS) + s) * HD + d) =
                        __floats2half2_rn(v0, v1);
                } else {
                    float* Y = (float*)Yv;
                    *(float2*)(Y + (size_t)m * DD + n) = make_float2(v0, v1);
                }
            }
        }
    }
}

// fused QKV: blockIdx.z selects {Q,K,V}
__global__ __launch_bounds__(256, 2) void gemm_qkv(
    const float* __restrict__ b0, const float* __restrict__ b1,
    const float* __restrict__ b2)
{
    __shared__ __half As[2 * 128 * GP];
    __shared__ __half Bs[2 * 128 * GP];
    const int z = blockIdx.z;
    const float* bias = (z == 0) ? b0 : (z == 1) ? b1 : b2;
    __half* Y = (z == 0) ? g_Qh : (z == 1) ? g_Kh : g_Vh;
    gemm_body(g_Xh, g_Wh[z], bias, Y, 0, As, Bs);
}

// output projection: ctx @ Wo^T + bo -> fp32 d_out
__global__ __launch_bounds__(256, 2) void gemm_out(
    const float* __restrict__ bias, float* __restrict__ out)
{
    __shared__ __half As[2 * 128 * GP];
    __shared__ __half Bs[2 * 128 * GP];
    gemm_body(g_Ch, g_Wh[3], bias, out, 1, As, Bs);
}

// ---------------- flash attention (fp16 mma, 128q/block, dbl-buffered K/V) --
#define KP 72   // halves; 144B rows -> conflict-free ldmatrix phases
#define KVSTRIDE (64 * KP)

__global__ __launch_bounds__(256, 2) void attn_h()
{
    // KV[0],KV[1] = K buffers; KV[2],KV[3] = V buffers. Q staged over KV[0..1].
    __shared__ __half KV[4 * KVSTRIDE];   // 36864 B

    const int tid  = threadIdx.x;
    const int lane = tid & 31;
    const int w    = tid >> 5;          // 0..7
    const int g    = lane >> 2;
    const int q    = lane & 3;
    const int qt   = blockIdx.x;        // 0..15 (128 queries each)
    const int bh   = blockIdx.y;        // 0..63
    const int frow  = lane & 15;
    const int fcol8 = (lane >> 4) * 8;

    const __half* Qg = g_Qh + (size_t)bh * SS * HD + (size_t)qt * 128 * HD;
    const __half* Kg = g_Kh + (size_t)bh * SS * HD;
    const __half* Vg = g_Vh + (size_t)bh * SS * HD;

    // ---- stage Q (128 x 64), build per-warp A frags -------------------------
    #pragma unroll
    for (int i = 0; i < 4; i++) {
        const int lin = tid + i * 256;          // 0..1023 16B chunks
        const int row = lin >> 3;
        const int c8  = (lin & 7) * 8;
        *(uint4*)(&KV[row * KP + c8]) = *(const uint4*)(Qg + row * HD + c8);
    }
    __syncthreads();

    uint32_t qa[4][4];
    #pragma unroll
    for (int kc = 0; kc < 4; kc++)
        ldm_x4(qa[kc], s2u(&KV[(w * 16 + frow) * KP + kc * 16 + fcol8]));
    __syncthreads();   // Q staging region free for K buffers

    float oc[8][4];
    #pragma unroll
    for (int nt = 0; nt < 8; nt++)
        #pragma unroll
        for (int e = 0; e < 4; e++) oc[nt][e] = 0.f;
    float m_lo = -1e30f, m_hi = -1e30f, l_lo = 0.f, l_hi = 0.f;

    const float CS = 0.125f * 1.44269504088896f;  // scale * log2(e)

    // prologue: stage kt=0 K/V into buffer 0
    #pragma unroll
    for (int i = 0; i < 2; i++) {
        const int lin = tid + i * 256;          // 0..511 chunks (64 rows x 8)
        const int row = lin >> 3;
        const int c8  = (lin & 7) * 8;
        cpa16(s2u(&KV[0 * KVSTRIDE + row * KP + c8]), Kg + (size_t)row * HD + c8);
        cpa16(s2u(&KV[2 * KVSTRIDE + row * KP + c8]), Vg + (size_t)row * HD + c8);
    }
    cpa_commit();

    for (int kt = 0; kt < SS / 64; kt++) {
        cpa_wait0();
        __syncthreads();
        const int buf = kt & 1;
        if (kt + 1 < SS / 64) {
            const size_t base = (size_t)(kt + 1) * 64 * HD;
            #pragma unroll
            for (int i = 0; i < 2; i++) {
                const int lin = tid + i * 256;
                const int row = lin >> 3;
                const int c8  = (lin & 7) * 8;
                cpa16(s2u(&KV[(buf ^ 1) * KVSTRIDE + row * KP + c8]),
                      Kg + base + (size_t)row * HD + c8);
                cpa16(s2u(&KV[(2 + (buf ^ 1)) * KVSTRIDE + row * KP + c8]),
                      Vg + base + (size_t)row * HD + c8);
            }
            cpa_commit();
        }
        const __half* Ks = &KV[buf * KVSTRIDE];
        const __half* Vs = &KV[(2 + buf) * KVSTRIDE];

        // ---- S = Q K^T (warp's 16 x 64) ------------------------------------
        float sc[8][4];
        #pragma unroll
        for (int nt = 0; nt < 8; nt++)
            #pragma unroll
            for (int e = 0; e < 4; e++) sc[nt][e] = 0.f;

        #pragma unroll
        for (int kc = 0; kc < 4; kc++) {
            const int kk = kc * 16 + fcol8;
            #pragma unroll
            for (int ng = 0; ng < 4; ng++) {
                uint32_t bk[4];
                ldm_x4(bk, s2u(&Ks[(ng * 16 + frow) * KP + kk]));
                mma16816(sc[ng * 2 + 0], qa[kc], bk[0], bk[2], sc[ng * 2 + 0]);
                mma16816(sc[ng * 2 + 1], qa[kc], bk[1], bk[3], sc[ng * 2 + 1]);
            }
        }

        // ---- online softmax in fragment layout (base-2 domain) -------------
        float tl = -1e30f, th = -1e30f;
        #pragma unroll
        for (int nt = 0; nt < 8; nt++) {
            sc[nt][0] *= CS; sc[nt][1] *= CS; sc[nt][2] *= CS; sc[nt][3] *= CS;
            tl = fmaxf(tl, fmaxf(sc[nt][0], sc[nt][1]));
            th = fmaxf(th, fmaxf(sc[nt][2], sc[nt][3]));
        }
        tl = fmaxf(tl, __shfl_xor_sync(0xffffffffu, tl, 1));
        tl = fmaxf(tl, __shfl_xor_sync(0xffffffffu, tl, 2));
        th = fmaxf(th, __shfl_xor_sync(0xffffffffu, th, 1));
        th = fmaxf(th, __shfl_xor_sync(0xffffffffu, th, 2));

        const float ml = fmaxf(m_lo, tl);
        const float mh = fmaxf(m_hi, th);
        const float al = ex2f(m_lo - ml);
        const float ah = ex2f(m_hi - mh);

        float suml = 0.f, sumh = 0.f;
        #pragma unroll
        for (int nt = 0; nt < 8; nt++) {
            sc[nt][0] = ex2f(sc[nt][0] - ml);
            sc[nt][1] = ex2f(sc[nt][1] - ml);
            sc[nt][2] = ex2f(sc[nt][2] - mh);
            sc[nt][3] = ex2f(sc[nt][3] - mh);
            suml += sc[nt][0] + sc[nt][1];
            sumh += sc[nt][2] + sc[nt][3];
        }
        suml += __shfl_xor_sync(0xffffffffu, suml, 1);
        suml += __shfl_xor_sync(0xffffffffu, suml, 2);
        sumh += __shfl_xor_sync(0xffffffffu, sumh, 1);
        sumh += __shfl_xor_sync(0xffffffffu, sumh, 2);

        l_lo = l_lo * al + suml;
        l_hi = l_hi * ah + sumh;
        m_lo = ml; m_hi = mh;

        #pragma unroll
        for (int nt = 0; nt < 8; nt++) {
            oc[nt][0] *= al; oc[nt][1] *= al;
            oc[nt][2] *= ah; oc[nt][3] *= ah;
        }

        // ---- O += P V (P: C-frag -> A-frag by register packing only) -------
        #pragma unroll
        for (int kc2 = 0; kc2 < 4; kc2++) {
            uint32_t pa[4];
            pa[0] = packh2(sc[2 * kc2][0],     sc[2 * kc2][1]);
            pa[1] = packh2(sc[2 * kc2][2],     sc[2 * kc2][3]);
            pa[2] = packh2(sc[2 * kc2 + 1][0], sc[2 * kc2 + 1][1]);
            pa[3] = packh2(sc[2 * kc2 + 1][2], sc[2 * kc2 + 1][3]);
            #pragma unroll
            for (int ng = 0; ng < 4; ng++) {
                uint32_t bv[4];
                ldm_x4t(bv, s2u(&Vs[(kc2 * 16 + frow) * KP + ng * 16 + fcol8]));
                mma16816(oc[ng * 2 + 0], pa, bv[0], bv[1], oc[ng * 2 + 0]);
                mma16816(oc[ng * 2 + 1], pa, bv[2], bv[3], oc[ng * 2 + 1]);
            }
        }
        // no trailing sync: next iter's head-sync guards buffer reuse
    }

    // ---- epilogue: normalize, write half ctx [b][s][h*64+d] -----------------
    const float il = 1.0f / l_lo;
    const float ih = 1.0f / l_hi;
    const int b = bh >> 4;
    const int h = bh & 15;
    const int row_lo = qt * 128 + w * 16 + g;
    #pragma unroll
    for (int nt = 0; nt < 8; nt++) {
        const int col = h * 64 + nt * 8 + 2 * q;
        *(__half2*)(g_Ch + ((size_t)b * SS + row_lo) * DD + col) =
            __floats2half2_rn(oc[nt][0] * il, oc[nt][1] * il);
        *(__half2*)(g_Ch + ((size_t)b * SS + row_lo + 8) * DD + col) =
            __floats2half2_rn(oc[nt][2] * ih, oc[nt][3] * ih);
    }
}

// ---------------- launch -----------------------------------------------------
extern "C" void kernel_launch(void* const* d_in, const int* in_sizes, int n_in,
                              void* d_out, int out_size)
{
    (void)in_sizes; (void)n_in; (void)out_size;
    const float* x  = (const float*)d_in[0];
    const float* Wq = (const float*)d_in[1];
    const float* bq = (const float*)d_in[2];
    const float* Wk = (const float*)d_in[3];
    const float* bk = (const float*)d_in[4];
    const float* Wv = (const float*)d_in[5];
    const float* bv = (const float*)d_in[6];
    const float* Wo = (const float*)d_in[7];
    const float* bo = (const float*)d_in[8];

    // convert x + all 4 weights in one launch (12288 blocks)
    f2h_all<<<8192 + 4 * 1024, 256>>>(x, Wq, Wk, Wv, Wo);

    gemm_qkv<<<dim3(DD / 128, MM / 128, 3), 256>>>(bq, bk, bv);

    attn_h<<<dim3(SS / 128, BB * HH), 256>>>();

    gemm_out<<<dim3(DD / 128, MM / 128), 256>>>(bo, (float*)d_out);
}

// round 9
// speedup vs baseline: 9.7440x; 1.1397x over previous
#include <cuda_runtime.h>
#include <cuda_fp16.h>
#include <math.h>
#include <stdint.h>

// Problem constants
#define BB 4
#define SS 2048
#define DD 1024
#define HH 16
#define HD 64
#define MM (BB*SS)          // 8192

// ---------------- scratch (device globals; no allocation allowed) ----------
__device__ __half g_Xh[(size_t)MM*DD];            // x in half
__device__ __half g_Wh[4][(size_t)DD*DD];         // Wq,Wk,Wv,Wo in half
__device__ __half g_Qh[(size_t)BB*HH*SS*HD];      // [b][h][s][d]
__device__ __half g_Kh[(size_t)BB*HH*SS*HD];
__device__ __half g_Vh[(size_t)BB*HH*SS*HD];
__device__ __half g_Ch[(size_t)MM*DD];            // ctx [b][s][h*64+d]

// ---------------- helpers ----------------------------------------------------
__device__ __forceinline__ uint32_t s2u(const void* p) {
    return (uint32_t)__cvta_generic_to_shared(p);
}
__device__ __forceinline__ void ldm_x4(uint32_t r[4], uint32_t a) {
    asm volatile("ldmatrix.sync.aligned.m8n8.x4.shared.b16 {%0,%1,%2,%3}, [%4];"
        : "=r"(r[0]), "=r"(r[1]), "=r"(r[2]), "=r"(r[3]) : "r"(a));
}
__device__ __forceinline__ void ldm_x4t(uint32_t r[4], uint32_t a) {
    asm volatile("ldmatrix.sync.aligned.m8n8.x4.trans.shared.b16 {%0,%1,%2,%3}, [%4];"
        : "=r"(r[0]), "=r"(r[1]), "=r"(r[2]), "=r"(r[3]) : "r"(a));
}
__device__ __forceinline__ void mma16816(float d[4], const uint32_t a[4],
                                         const uint32_t b0, const uint32_t b1,
                                         const float c[4]) {
    asm volatile("mma.sync.aligned.m16n8k16.row.col.f32.f16.f16.f32 "
        "{%0,%1,%2,%3},{%4,%5,%6,%7},{%8,%9},{%10,%11,%12,%13};"
        : "=f"(d[0]), "=f"(d[1]), "=f"(d[2]), "=f"(d[3])
        : "r"(a[0]), "r"(a[1]), "r"(a[2]), "r"(a[3]), "r"(b0), "r"(b1),
          "f"(c[0]), "f"(c[1]), "f"(c[2]), "f"(c[3]));
}
__device__ __forceinline__ uint32_t packh2(float x, float y) {
    __half2 h = __floats2half2_rn(x, y);
    return *reinterpret_cast<uint32_t*>(&h);
}
__device__ __forceinline__ float ex2f(float x) {
    float r; asm("ex2.approx.ftz.f32 %0, %1;" : "=f"(r) : "f"(x)); return r;
}
__device__ __forceinline__ void cpa16(uint32_t d, const void* g) {
    asm volatile("cp.async.cg.shared.global [%0], [%1], 16;" :: "r"(d), "l"(g));
}
__device__ __forceinline__ void cpa_commit() { asm volatile("cp.async.commit_group;"); }
__device__ __forceinline__ void cpa_wait0()  { asm volatile("cp.async.wait_group 0;"); }
__device__ __forceinline__ void cpa_wait1()  { asm volatile("cp.async.wait_group 1;"); }
__device__ __forceinline__ uint32_t sw128(uint32_t off) {
    return off ^ ((off >> 3) & 0x70);
}

// ---------------- fp32 -> fp16 conversion (all 5 tensors, one launch) --------
__global__ __launch_bounds__(256) void f2h_all(
    const float* __restrict__ x,
    const float* __restrict__ w0, const float* __restrict__ w1,
    const float* __restrict__ w2, const float* __restrict__ w3)
{
    const float* src;
    __half* dst;
    int chunk;
    if (blockIdx.x < 8192) {
        src = x; dst = g_Xh; chunk = blockIdx.x;
    } else {
        const int wi = (blockIdx.x - 8192) >> 10;
        chunk = (blockIdx.x - 8192) & 1023;
        src = (wi == 0) ? w0 : (wi == 1) ? w1 : (wi == 2) ? w2 : w3;
        dst = g_Wh[wi];
    }
    const int i = (chunk * 256 + threadIdx.x) * 4;
    float4 v = *(const float4*)(src + i);
    *(__half2*)(dst + i)     = __floats2half2_rn(v.x, v.y);
    *(__half2*)(dst + i + 2) = __floats2half2_rn(v.z, v.w);
}

// ---------------- GEMM body: K-chunk 64, 3-stage cp.async, SW128 swizzle ----
// Y[m][n] = sum_k X[m][k] * W[n][k] + bias[n]
// mode 0: scatter half to [B,H,S,HD].  mode 1: row-major fp32 [M,N].
// Dynamic smem: 3 stages x (A 16KB + B 16KB) = 96KB.
#define GSTAGE 32768           // bytes per stage (A+B)
#define GASZ   16384           // bytes of A within a stage
#define NKIT   (DD / 64)       // 16

__device__ __forceinline__ void gemm_stage(
    uint32_t aB, uint32_t bB, const __half* X, const __half* W,
    int bm, int bn, int k0, int tid)
{
    #pragma unroll
    for (int i = 0; i < 4; i++) {
        const int lin = tid + i * 256;          // 0..1023
        const int row = lin >> 3;
        const int c16 = lin & 7;
        const uint32_t sw = sw128(row * 128 + c16 * 16);
        cpa16(aB + sw, X + (size_t)(bm + row) * DD + k0 + c16 * 8);
        cpa16(bB + sw, W + (size_t)(bn + row) * DD + k0 + c16 * 8);
    }
    cpa_commit();
}

__device__ __forceinline__ void gemm_body(
    const __half* __restrict__ X, const __half* __restrict__ W,
    const float* __restrict__ bias, void* __restrict__ Yv, int mode,
    uint32_t sbase)
{
    const int tid  = threadIdx.x;
    const int lane = tid & 31;
    const int wid  = tid >> 5;
    const int wm   = wid & 3;           // 4 warp rows of 32
    const int wn   = wid >> 2;          // 2 warp cols of 64
    const int g    = lane >> 2;
    const int q    = lane & 3;
    const int bm   = blockIdx.y * 128;
    const int bn   = blockIdx.x * 128;

    const int frow  = lane & 15;        // ldmatrix row within 16
    const int fbyte = (lane >> 4) * 16; // ldmatrix 16B-chunk select

    float acc[2][8][4];
    #pragma unroll
    for (int rg = 0; rg < 2; rg++)
        #pragma unroll
        for (int nt = 0; nt < 8; nt++)
            #pragma unroll
            for (int e = 0; e < 4; e++) acc[rg][nt][e] = 0.f;

    // prologue: stage chunks 0,1
    gemm_stage(sbase, sbase + GASZ, X, W, bm, bn, 0, tid);
    gemm_stage(sbase + GSTAGE, sbase + GSTAGE + GASZ, X, W, bm, bn, 64, tid);

    int buf = 0;
    for (int it = 0; it < NKIT; it++) {
        if (it + 2 < NKIT) cpa_wait1(); else cpa_wait0();
        __syncthreads();
        if (it + 2 < NKIT) {
            const int pb = (it + 2) % 3;
            gemm_stage(sbase + pb * GSTAGE, sbase + pb * GSTAGE + GASZ,
                       X, W, bm, bn, (it + 2) * 64, tid);
        }
        const uint32_t aB = sbase + buf * GSTAGE;
        const uint32_t bB = aB + GASZ;

        #pragma unroll
        for (int s = 0; s < 4; s++) {
            const uint32_t kb = s * 32 + fbyte;
            uint32_t af[2][4], bq4[4][4];
            #pragma unroll
            for (int rg = 0; rg < 2; rg++)
                ldm_x4(af[rg], aB + sw128((wm * 32 + rg * 16 + frow) * 128 + kb));
            #pragma unroll
            for (int ng = 0; ng < 4; ng++)
                ldm_x4(bq4[ng], bB + sw128((wn * 64 + ng * 16 + frow) * 128 + kb));
            #pragma unroll
            for (int rg = 0; rg < 2; rg++)
                #pragma unroll
                for (int ng = 0; ng < 4; ng++) {
                    mma16816(acc[rg][ng * 2 + 0], af[rg], bq4[ng][0], bq4[ng][2],
                             acc[rg][ng * 2 + 0]);
                    mma16816(acc[rg][ng * 2 + 1], af[rg], bq4[ng][1], bq4[ng][3],
                             acc[rg][ng * 2 + 1]);
                }
        }
        buf = (buf + 1) % 3;
        // barrier at next iteration's head protects buffer reuse
    }

    // epilogue: c0:(g,2q) c1:(g,2q+1) c2:(g+8,2q) c3:(g+8,2q+1)
    #pragma unroll
    for (int rg = 0; rg < 2; rg++) {
        #pragma unroll
        for (int nt = 0; nt < 8; nt++) {
            const int n = bn + wn * 64 + nt * 8 + 2 * q;
            const float b0 = __ldg(&bias[n]);
            const float b1 = __ldg(&bias[n + 1]);
            #pragma unroll
            for (int half_ = 0; half_ < 2; half_++) {
                const int m = bm + wm * 32 + rg * 16 + g + half_ * 8;
                const float v0 = acc[rg][nt][half_ * 2 + 0] + b0;
                const float v1 = acc[rg][nt][half_ * 2 + 1] + b1;
                if (mode == 0) {
                    const int bb = m >> 11;
                    const int s  = m & 2047;
                    const int h  = n >> 6;
                    const int d  = n & 63;
                    __half* Y = (__half*)Yv;
                    *(__half2*)(Y + ((((size_t)bb * HH + h) * SS) + s) * HD + d) =
                        __floats2half2_rn(v0, v1);
                } else {
                    float* Y = (float*)Yv;
                    *(float2*)(Y + (size_t)m * DD + n) = make_float2(v0, v1);
                }
            }
        }
    }
}

// fused QKV: blockIdx.z selects {Q,K,V}
__global__ __launch_bounds__(256, 2) void gemm_qkv(
    const float* __restrict__ b0, const float* __restrict__ b1,
    const float* __restrict__ b2)
{
    extern __shared__ __align__(1024) __half dsm[];
    const int z = blockIdx.z;
    const float* bias = (z == 0) ? b0 : (z == 1) ? b1 : b2;
    __half* Y = (z == 0) ? g_Qh : (z == 1) ? g_Kh : g_Vh;
    gemm_body(g_Xh, g_Wh[z], bias, Y, 0, s2u(dsm));
}

// output projection: ctx @ Wo^T + bo -> fp32 d_out
__global__ __launch_bounds__(256, 2) void gemm_out(
    const float* __restrict__ bias, float* __restrict__ out)
{
    extern __shared__ __align__(1024) __half dsm[];
    gemm_body(g_Ch, g_Wh[3], bias, out, 1, s2u(dsm));
}

// ---------------- flash attention (fp16 mma, 128q/block, dbl-buffered K/V) --
#define KP 72   // halves; 144B rows -> conflict-free ldmatrix phases
#define KVSTRIDE (64 * KP)

__global__ __launch_bounds__(256, 2) void attn_h()
{
    __shared__ __half KV[4 * KVSTRIDE];   // 36864 B

    const int tid  = threadIdx.x;
    const int lane = tid & 31;
    const int w    = tid >> 5;          // 0..7
    const int g    = lane >> 2;
    const int q    = lane & 3;
    const int qt   = blockIdx.x;        // 0..15 (128 queries each)
    const int bh   = blockIdx.y;        // 0..63
    const int frow  = lane & 15;
    const int fcol8 = (lane >> 4) * 8;

    const __half* Qg = g_Qh + (size_t)bh * SS * HD + (size_t)qt * 128 * HD;
    const __half* Kg = g_Kh + (size_t)bh * SS * HD;
    const __half* Vg = g_Vh + (size_t)bh * SS * HD;

    #pragma unroll
    for (int i = 0; i < 4; i++) {
        const int lin = tid + i * 256;
        const int row = lin >> 3;
        const int c8  = (lin & 7) * 8;
        *(uint4*)(&KV[row * KP + c8]) = *(const uint4*)(Qg + row * HD + c8);
    }
    __syncthreads();

    uint32_t qa[4][4];
    #pragma unroll
    for (int kc = 0; kc < 4; kc++)
        ldm_x4(qa[kc], s2u(&KV[(w * 16 + frow) * KP + kc * 16 + fcol8]));
    __syncthreads();

    float oc[8][4];
    #pragma unroll
    for (int nt = 0; nt < 8; nt++)
        #pragma unroll
        for (int e = 0; e < 4; e++) oc[nt][e] = 0.f;
    float m_lo = -1e30f, m_hi = -1e30f, l_lo = 0.f, l_hi = 0.f;

    const float CS = 0.125f * 1.44269504088896f;

    #pragma unroll
    for (int i = 0; i < 2; i++) {
        const int lin = tid + i * 256;
        const int row = lin >> 3;
        const int c8  = (lin & 7) * 8;
        cpa16(s2u(&KV[0 * KVSTRIDE + row * KP + c8]), Kg + (size_t)row * HD + c8);
        cpa16(s2u(&KV[2 * KVSTRIDE + row * KP + c8]), Vg + (size_t)row * HD + c8);
    }
    cpa_commit();

    for (int kt = 0; kt < SS / 64; kt++) {
        cpa_wait0();
        __syncthreads();
        const int buf = kt & 1;
        if (kt + 1 < SS / 64) {
            const size_t base = (size_t)(kt + 1) * 64 * HD;
            #pragma unroll
            for (int i = 0; i < 2; i++) {
                const int lin = tid + i * 256;
                const int row = lin >> 3;
                const int c8  = (lin & 7) * 8;
                cpa16(s2u(&KV[(buf ^ 1) * KVSTRIDE + row * KP + c8]),
                      Kg + base + (size_t)row * HD + c8);
                cpa16(s2u(&KV[(2 + (buf ^ 1)) * KVSTRIDE + row * KP + c8]),
                      Vg + base + (size_t)row * HD + c8);
            }
            cpa_commit();
        }
        const __half* Ks = &KV[buf * KVSTRIDE];
        const __half* Vs = &KV[(2 + buf) * KVSTRIDE];

        float sc[8][4];
        #pragma unroll
        for (int nt = 0; nt < 8; nt++)
            #pragma unroll
            for (int e = 0; e < 4; e++) sc[nt][e] = 0.f;

        #pragma unroll
        for (int kc = 0; kc < 4; kc++) {
            const int kk = kc * 16 + fcol8;
            #pragma unroll
            for (int ng = 0; ng < 4; ng++) {
                uint32_t bk[4];
                ldm_x4(bk, s2u(&Ks[(ng * 16 + frow) * KP + kk]));
                mma16816(sc[ng * 2 + 0], qa[kc], bk[0], bk[2], sc[ng * 2 + 0]);
                mma16816(sc[ng * 2 + 1], qa[kc], bk[1], bk[3], sc[ng * 2 + 1]);
            }
        }

        float tl = -1e30f, th = -1e30f;
        #pragma unroll
        for (int nt = 0; nt < 8; nt++) {
            sc[nt][0] *= CS; sc[nt][1] *= CS; sc[nt][2] *= CS; sc[nt][3] *= CS;
            tl = fmaxf(tl, fmaxf(sc[nt][0], sc[nt][1]));
            th = fmaxf(th, fmaxf(sc[nt][2], sc[nt][3]));
        }
        tl = fmaxf(tl, __shfl_xor_sync(0xffffffffu, tl, 1));
        tl = fmaxf(tl, __shfl_xor_sync(0xffffffffu, tl, 2));
        th = fmaxf(th, __shfl_xor_sync(0xffffffffu, th, 1));
        th = fmaxf(th, __shfl_xor_sync(0xffffffffu, th, 2));

        const float ml = fmaxf(m_lo, tl);
        const float mh = fmaxf(m_hi, th);
        const float al = ex2f(m_lo - ml);
        const float ah = ex2f(m_hi - mh);

        float suml = 0.f, sumh = 0.f;
        #pragma unroll
        for (int nt = 0; nt < 8; nt++) {
            sc[nt][0] = ex2f(sc[nt][0] - ml);
            sc[nt][1] = ex2f(sc[nt][1] - ml);
            sc[nt][2] = ex2f(sc[nt][2] - mh);
            sc[nt][3] = ex2f(sc[nt][3] - mh);
            suml += sc[nt][0] + sc[nt][1];
            sumh += sc[nt][2] + sc[nt][3];
        }
        suml += __shfl_xor_sync(0xffffffffu, suml, 1);
        suml += __shfl_xor_sync(0xffffffffu, suml, 2);
        sumh += __shfl_xor_sync(0xffffffffu, sumh, 1);
        sumh += __shfl_xor_sync(0xffffffffu, sumh, 2);

        l_lo = l_lo * al + suml;
        l_hi = l_hi * ah + sumh;
        m_lo = ml; m_hi = mh;

        #pragma unroll
        for (int nt = 0; nt < 8; nt++) {
            oc[nt][0] *= al; oc[nt][1] *= al;
            oc[nt][2] *= ah; oc[nt][3] *= ah;
        }

        #pragma unroll
        for (int kc2 = 0; kc2 < 4; kc2++) {
            uint32_t pa[4];
            pa[0] = packh2(sc[2 * kc2][0],     sc[2 * kc2][1]);
            pa[1] = packh2(sc[2 * kc2][2],     sc[2 * kc2][3]);
            pa[2] = packh2(sc[2 * kc2 + 1][0], sc[2 * kc2 + 1][1]);
            pa[3] = packh2(sc[2 * kc2 + 1][2], sc[2 * kc2 + 1][3]);
            #pragma unroll
            for (int ng = 0; ng < 4; ng++) {
                uint32_t bv[4];
                ldm_x4t(bv, s2u(&Vs[(kc2 * 16 + frow) * KP + ng * 16 + fcol8]));
                mma16816(oc[ng * 2 + 0], pa, bv[0], bv[1], oc[ng * 2 + 0]);
                mma16816(oc[ng * 2 + 1], pa, bv[2], bv[3], oc[ng * 2 + 1]);
            }
        }
    }

    const float il = 1.0f / l_lo;
    const float ih = 1.0f / l_hi;
    const int b = bh >> 4;
    const int h = bh & 15;
    const int row_lo = qt * 128 + w * 16 + g;
    #pragma unroll
    for (int nt = 0; nt < 8; nt++) {
        const int col = h * 64 + nt * 8 + 2 * q;
        *(__half2*)(g_Ch + ((size_t)b * SS + row_lo) * DD + col) =
            __floats2half2_rn(oc[nt][0] * il, oc[nt][1] * il);
        *(__half2*)(g_Ch + ((size_t)b * SS + row_lo + 8) * DD + col) =
            __floats2half2_rn(oc[nt][2] * ih, oc[nt][3] * ih);
    }
}

// ---------------- launch -----------------------------------------------------
#define GEMM_SMEM (3 * GSTAGE)   // 98304 bytes

extern "C" void kernel_launch(void* const* d_in, const int* in_sizes, int n_in,
                              void* d_out, int out_size)
{
    (void)in_sizes; (void)n_in; (void)out_size;
    const float* x  = (const float*)d_in[0];
    const float* Wq = (const float*)d_in[1];
    const float* bq = (const float*)d_in[2];
    const float* Wk = (const float*)d_in[3];
    const float* bk = (const float*)d_in[4];
    const float* Wv = (const float*)d_in[5];
    const float* bv = (const float*)d_in[6];
    const float* Wo = (const float*)d_in[7];
    const float* bo = (const float*)d_in[8];

    cudaFuncSetAttribute(gemm_qkv, cudaFuncAttributeMaxDynamicSharedMemorySize,
                         GEMM_SMEM);
    cudaFuncSetAttribute(gemm_out, cudaFuncAttributeMaxDynamicSharedMemorySize,
                         GEMM_SMEM);

    // convert x + all 4 weights in one launch (12288 blocks)
    f2h_all<<<8192 + 4 * 1024, 256>>>(x, Wq, Wk, Wv, Wo);

    gemm_qkv<<<dim3(DD / 128, MM / 128, 3), 256, GEMM_SMEM>>>(bq, bk, bv);

    attn_h<<<dim3(SS / 128, BB * HH), 256>>>();

    gemm_out<<<dim3(DD / 128, MM / 128), 256, GEMM_SMEM>>>(bo, (float*)d_out);
}